// round 1
// baseline (speedup 1.0000x reference)
#include <cuda_runtime.h>

#define BB 2
#define SS 4096
#define DD 768
#define HH 12
#define HD 64
#define N3 (3*DD)
#define MM (BB*SS)

// Scratch (device globals; no allocation allowed)
__device__ __align__(16) float g_q[BB*HH*SS*HD];
__device__ __align__(16) float g_k[BB*HH*SS*HD];
__device__ __align__(16) float g_v[BB*HH*SS*HD];
__device__ __align__(16) float g_att[MM*DD];

// ---------------------------------------------------------------------------
// GEMM1: qkv = x @ Wqkv + bqkv, scattered into g_q/g_k/g_v as [B,H,S,hd]
// BM=BN=64, BK=16, 256 threads, 4x4 micro-tile
// ---------------------------------------------------------------------------
__global__ __launch_bounds__(256) void gemm_qkv_kernel(
    const float* __restrict__ X, const float* __restrict__ W,
    const float* __restrict__ bias)
{
    __shared__ __align__(16) float As[16][64];
    __shared__ __align__(16) float Bs[16][64];
    const int tid = threadIdx.x;
    const int col0 = blockIdx.x * 64;
    const int row0 = blockIdx.y * 64;
    const int ty = tid >> 4, tx = tid & 15;

    const int arow = tid >> 2;
    const int ak   = (tid & 3) * 4;
    const int brow = tid >> 4;
    const int bcol = (tid & 15) * 4;

    float acc[4][4] = {};

    for (int k0 = 0; k0 < DD; k0 += 16) {
        float4 av = *(const float4*)&X[(row0 + arow) * DD + k0 + ak];
        float4 bv = *(const float4*)&W[(k0 + brow) * N3 + col0 + bcol];
        As[ak + 0][arow] = av.x;
        As[ak + 1][arow] = av.y;
        As[ak + 2][arow] = av.z;
        As[ak + 3][arow] = av.w;
        *(float4*)&Bs[brow][bcol] = bv;
        __syncthreads();
#pragma unroll
        for (int kk = 0; kk < 16; kk++) {
            float4 a = *(const float4*)&As[kk][ty * 4];
            float4 b = *(const float4*)&Bs[kk][tx * 4];
            float ar[4] = {a.x, a.y, a.z, a.w};
            float br[4] = {b.x, b.y, b.z, b.w};
#pragma unroll
            for (int i = 0; i < 4; i++)
#pragma unroll
                for (int j = 0; j < 4; j++)
                    acc[i][j] += ar[i] * br[j];
        }
        __syncthreads();
    }

    // Epilogue: bias add + scatter. Block col tile lies entirely inside one
    // (which, head): which = bx/12, head = bx%12, d = tx*4+j.
    const int which = blockIdx.x / HH;
    const int h     = blockIdx.x % HH;
    float* dst = (which == 0) ? g_q : (which == 1) ? g_k : g_v;
    float4 bb = *(const float4*)&bias[col0 + tx * 4];
#pragma unroll
    for (int i = 0; i < 4; i++) {
        int r  = row0 + ty * 4 + i;
        int b_ = r >> 12;       // / 4096
        int s_ = r & 4095;
        float4 v;
        v.x = acc[i][0] + bb.x;
        v.y = acc[i][1] + bb.y;
        v.z = acc[i][2] + bb.z;
        v.w = acc[i][3] + bb.w;
        *(float4*)&dst[((b_ * HH + h) * SS + s_) * HD + tx * 4] = v;
    }
}

// ---------------------------------------------------------------------------
// Flash attention: one CTA per (64-query tile, b*h). 256 threads.
// Thread (r = tid/4, q = tid%4): owns row r; S-cols c = j*4+q (interleaved),
// O-cols dd = q*16..q*16+15 (blocked, for float4 V reads).
// ---------------------------------------------------------------------------
#define KS_STRIDE 68
#define PS_STRIDE 68
#define ATTN_SMEM ((64*KS_STRIDE + 64*PS_STRIDE + 64*64) * 4)

__global__ __launch_bounds__(256, 2) void attn_kernel()
{
    extern __shared__ float sm[];
    float* Ks = sm;                         // [64][68]
    float* Ps = sm + 64 * KS_STRIDE;        // [64][68]
    float* Vs = sm + 64 * (KS_STRIDE + PS_STRIDE); // [64][64]

    const int qt  = blockIdx.x;
    const int bh  = blockIdx.y;
    const int tid = threadIdx.x;
    const int r   = tid >> 2;
    const int q   = tid & 3;

    const float* Qb = g_q + (size_t)bh * SS * HD;
    const float* Kb = g_k + (size_t)bh * SS * HD;
    const float* Vb = g_v + (size_t)bh * SS * HD;

    const int grow = qt * 64 + r;

    // Q row in registers, pre-scaled by hd^-0.5 = 0.125
    float4 qreg[16];
    const float4* Qrow = (const float4*)(Qb + grow * HD);
#pragma unroll
    for (int i = 0; i < 16; i++) {
        float4 t = Qrow[i];
        t.x *= 0.125f; t.y *= 0.125f; t.z *= 0.125f; t.w *= 0.125f;
        qreg[i] = t;
    }

    float m = -1e30f, l = 0.f;
    float4 o[4];
#pragma unroll
    for (int i = 0; i < 4; i++) o[i] = make_float4(0.f, 0.f, 0.f, 0.f);

    for (int kt = 0; kt <= qt; kt++) {
        __syncthreads();   // previous tile fully consumed
        {
            const float4* Kg = (const float4*)(Kb + kt * 64 * HD);
            const float4* Vg = (const float4*)(Vb + kt * 64 * HD);
#pragma unroll
            for (int i = 0; i < 4; i++) {
                int f   = tid + i * 256;      // 0..1023 float4s
                int row = f >> 4;
                int c4  = (f & 15) * 4;
                *(float4*)&Ks[row * KS_STRIDE + c4] = Kg[f];
                *(float4*)&Vs[row * 64 + c4]        = Vg[f];
            }
        }
        __syncthreads();

        // S = Q K^T for this thread's 16 cols (c = j*4+q)
        float s[16];
#pragma unroll
        for (int j = 0; j < 16; j++) {
            int c = j * 4 + q;
            const float4* Kr = (const float4*)&Ks[c * KS_STRIDE];
            float4 a = make_float4(0.f, 0.f, 0.f, 0.f);
#pragma unroll
            for (int d4 = 0; d4 < 16; d4++) {
                float4 kv = Kr[d4];
                a.x += qreg[d4].x * kv.x;
                a.y += qreg[d4].y * kv.y;
                a.z += qreg[d4].z * kv.z;
                a.w += qreg[d4].w * kv.w;
            }
            s[j] = (a.x + a.y) + (a.z + a.w);
        }

        if (kt == qt) {     // causal mask on diagonal tile
#pragma unroll
            for (int j = 0; j < 16; j++) {
                int c = kt * 64 + j * 4 + q;
                if (c > grow) s[j] = -1e30f;
            }
        }

        // online softmax (quad reduction over the 4 threads of this row)
        float mt = s[0];
#pragma unroll
        for (int j = 1; j < 16; j++) mt = fmaxf(mt, s[j]);
        mt = fmaxf(mt, __shfl_xor_sync(0xffffffffu, mt, 1));
        mt = fmaxf(mt, __shfl_xor_sync(0xffffffffu, mt, 2));
        float mn = fmaxf(m, mt);

        float lt = 0.f;
#pragma unroll
        for (int j = 0; j < 16; j++) {
            float p = __expf(s[j] - mn);
            lt += p;
            Ps[r * PS_STRIDE + j * 4 + q] = p;
        }
        lt += __shfl_xor_sync(0xffffffffu, lt, 1);
        lt += __shfl_xor_sync(0xffffffffu, lt, 2);

        float alpha = __expf(m - mn);
        m = mn;
        l = l * alpha + lt;
#pragma unroll
        for (int i = 0; i < 4; i++) {
            o[i].x *= alpha; o[i].y *= alpha; o[i].z *= alpha; o[i].w *= alpha;
        }
        __syncwarp();      // quad's Ps writes visible

        // O += P @ V  (dd = q*16 + 0..15, float4 V reads)
#pragma unroll 4
        for (int c = 0; c < 64; c++) {
            float p = Ps[r * PS_STRIDE + c];
            const float4* Vr = (const float4*)&Vs[c * 64 + q * 16];
#pragma unroll
            for (int i = 0; i < 4; i++) {
                float4 vv = Vr[i];
                o[i].x += p * vv.x;
                o[i].y += p * vv.y;
                o[i].z += p * vv.z;
                o[i].w += p * vv.w;
            }
        }
    }

    float inv = 1.f / l;
    int b_ = bh / HH, h_ = bh % HH;
    float* dst = g_att + (size_t)(b_ * SS + grow) * DD + h_ * HD + q * 16;
#pragma unroll
    for (int i = 0; i < 4; i++) {
        float4 v = o[i];
        v.x *= inv; v.y *= inv; v.z *= inv; v.w *= inv;
        *(float4*)&dst[i * 4] = v;
    }
}

// ---------------------------------------------------------------------------
// GEMM2: out = g_att @ Wout + bout  -> d_out [8192, 768]
// ---------------------------------------------------------------------------
__global__ __launch_bounds__(256) void gemm_out_kernel(
    const float* __restrict__ W, const float* __restrict__ bias,
    float* __restrict__ Y)
{
    __shared__ __align__(16) float As[16][64];
    __shared__ __align__(16) float Bs[16][64];
    const int tid = threadIdx.x;
    const int col0 = blockIdx.x * 64;
    const int row0 = blockIdx.y * 64;
    const int ty = tid >> 4, tx = tid & 15;

    const int arow = tid >> 2;
    const int ak   = (tid & 3) * 4;
    const int brow = tid >> 4;
    const int bcol = (tid & 15) * 4;

    float acc[4][4] = {};

    for (int k0 = 0; k0 < DD; k0 += 16) {
        float4 av = *(const float4*)&g_att[(size_t)(row0 + arow) * DD + k0 + ak];
        float4 bv = *(const float4*)&W[(k0 + brow) * DD + col0 + bcol];
        As[ak + 0][arow] = av.x;
        As[ak + 1][arow] = av.y;
        As[ak + 2][arow] = av.z;
        As[ak + 3][arow] = av.w;
        *(float4*)&Bs[brow][bcol] = bv;
        __syncthreads();
#pragma unroll
        for (int kk = 0; kk < 16; kk++) {
            float4 a = *(const float4*)&As[kk][ty * 4];
            float4 b = *(const float4*)&Bs[kk][tx * 4];
            float ar[4] = {a.x, a.y, a.z, a.w};
            float br[4] = {b.x, b.y, b.z, b.w};
#pragma unroll
            for (int i = 0; i < 4; i++)
#pragma unroll
                for (int j = 0; j < 4; j++)
                    acc[i][j] += ar[i] * br[j];
        }
        __syncthreads();
    }

    float4 bb = *(const float4*)&bias[col0 + tx * 4];
#pragma unroll
    for (int i = 0; i < 4; i++) {
        int r = row0 + ty * 4 + i;
        float4 v;
        v.x = acc[i][0] + bb.x;
        v.y = acc[i][1] + bb.y;
        v.z = acc[i][2] + bb.z;
        v.w = acc[i][3] + bb.w;
        *(float4*)&Y[(size_t)r * DD + col0 + tx * 4] = v;
    }
}

// ---------------------------------------------------------------------------
extern "C" void kernel_launch(void* const* d_in, const int* in_sizes, int n_in,
                              void* d_out, int out_size)
{
    const float* x    = (const float*)d_in[0];
    const float* Wqkv = (const float*)d_in[1];
    const float* bqkv = (const float*)d_in[2];
    const float* Wout = (const float*)d_in[3];
    const float* bout = (const float*)d_in[4];
    float* out = (float*)d_out;

    cudaFuncSetAttribute(attn_kernel,
                         cudaFuncAttributeMaxDynamicSharedMemorySize, ATTN_SMEM);

    gemm_qkv_kernel<<<dim3(N3 / 64, MM / 64), 256>>>(x, Wqkv, bqkv);
    attn_kernel<<<dim3(SS / 64, BB * HH), 256, ATTN_SMEM>>>();
    gemm_out_kernel<<<dim3(DD / 64, MM / 64), 256>>>(Wout, bout, out);
}

// round 2
// speedup vs baseline: 1.5888x; 1.5888x over previous
#include <cuda_runtime.h>

#define BB 2
#define SS 4096
#define DD 768
#define HH 12
#define HD 64
#define N3 (3*DD)
#define MM (BB*SS)

// Scratch (device globals). Q,K stored d-major: [b,h,d,s]; V row-major: [b,h,s,d]
__device__ __align__(16) float g_q[BB*HH*HD*SS];
__device__ __align__(16) float g_k[BB*HH*HD*SS];
__device__ __align__(16) float g_v[BB*HH*SS*HD];
__device__ __align__(16) float g_att[MM*DD];

// ---------------------------------------------------------------------------
// GEMM1: qkv = x @ Wqkv + bqkv. 128x128x8 tiles, 256 thr, 8x8 micro-tile.
// Epilogue scatters Q,K d-major and V row-major.
// ---------------------------------------------------------------------------
__global__ __launch_bounds__(256, 2) void gemm_qkv_kernel(
    const float* __restrict__ X, const float* __restrict__ W,
    const float* __restrict__ bias)
{
    __shared__ __align__(16) float As[8][132];
    __shared__ __align__(16) float Bs[8][128];
    const int tid  = threadIdx.x;
    const int col0 = blockIdx.x * 128;
    const int row0 = blockIdx.y * 128;
    const int ty = tid >> 4, tx = tid & 15;

    const int arow = tid >> 1;
    const int ak   = (tid & 1) * 4;
    const int brow = tid >> 5;
    const int bcol = (tid & 31) * 4;

    const float* Ap = X + (size_t)(row0 + arow) * DD + ak;
    const float* Bp = W + (size_t)brow * N3 + col0 + bcol;

    float4 av = *(const float4*)Ap;
    float4 bv = *(const float4*)Bp;

    float acc[8][8] = {};

    for (int k0 = 0; k0 < DD; k0 += 8) {
        As[ak + 0][arow] = av.x;
        As[ak + 1][arow] = av.y;
        As[ak + 2][arow] = av.z;
        As[ak + 3][arow] = av.w;
        *(float4*)&Bs[brow][bcol] = bv;
        __syncthreads();
        if (k0 + 8 < DD) {
            av = *(const float4*)(Ap + k0 + 8);
            bv = *(const float4*)(Bp + (size_t)(k0 + 8) * N3);
        }
#pragma unroll
        for (int kk = 0; kk < 8; kk++) {
            float4 a0 = *(const float4*)&As[kk][ty * 4];
            float4 a1 = *(const float4*)&As[kk][64 + ty * 4];
            float4 b0 = *(const float4*)&Bs[kk][tx * 4];
            float4 b1 = *(const float4*)&Bs[kk][64 + tx * 4];
            float ar[8] = {a0.x,a0.y,a0.z,a0.w,a1.x,a1.y,a1.z,a1.w};
            float br[8] = {b0.x,b0.y,b0.z,b0.w,b1.x,b1.y,b1.z,b1.w};
#pragma unroll
            for (int i = 0; i < 8; i++)
#pragma unroll
                for (int j = 0; j < 8; j++)
                    acc[i][j] += ar[i] * br[j];
        }
        __syncthreads();
    }

    // Epilogue: col0..col0+127 lies within one 'which' (768 % 128 == 0).
    const int which = col0 / DD;
    float* qk_dst = (which == 0) ? g_q : g_k;

#pragma unroll
    for (int g = 0; g < 2; g++) {
        const int cbase = col0 + g * 64;       // one head per 64-col group
        const int h = (cbase % DD) / HD;
        if (which == 2) {
            // V: row-major [b,h,s,d]
#pragma unroll
            for (int i = 0; i < 8; i++) {
                int r  = row0 + ((i < 4) ? ty * 4 + i : 64 + ty * 4 + i - 4);
                int b_ = r >> 12, s_ = r & 4095;
                float4 v;
                v.x = acc[i][g*4+0] + bias[cbase + tx*4 + 0];
                v.y = acc[i][g*4+1] + bias[cbase + tx*4 + 1];
                v.z = acc[i][g*4+2] + bias[cbase + tx*4 + 2];
                v.w = acc[i][g*4+3] + bias[cbase + tx*4 + 3];
                *(float4*)&g_v[(((size_t)(b_*HH + h) * SS + s_) * HD) + tx*4] = v;
            }
        } else {
            // Q/K: d-major [b,h,d,s]
#pragma unroll
            for (int jj = 0; jj < 4; jj++) {
                int d  = tx * 4 + jj;
                float bb = bias[cbase + d];
#pragma unroll
                for (int i = 0; i < 8; i++) {
                    int r  = row0 + ((i < 4) ? ty * 4 + i : 64 + ty * 4 + i - 4);
                    int b_ = r >> 12, s_ = r & 4095;
                    qk_dst[((size_t)((b_*HH + h) * HD + d)) * SS + s_] =
                        acc[i][g*4+jj] + bb;
                }
            }
        }
    }
}

// ---------------------------------------------------------------------------
// Flash attention, SGEMM-style. One CTA per (64-q tile, b*h). 256 threads.
// Thread (ty=tid/16, tx=tid%16) owns S/O micro-tile rows ty*4..+3, cols tx*4..+3.
// Q,K d-major in gmem -> rank-1 updates with contiguous float4 smem reads.
// ---------------------------------------------------------------------------
#define AST 68
#define ATTN_SMEM (4 * 64 * AST * 4)

__global__ __launch_bounds__(256, 2) void attn_kernel()
{
    extern __shared__ float sm[];
    float* Qs = sm;                 // [64 d][68]
    float* Ks = sm + 64 * AST;      // [64 d][68]
    float* Vs = sm + 2 * 64 * AST;  // [64 c][68]
    float* Ps = sm + 3 * 64 * AST;  // [64 c][68] (transposed: [c][row])

    const int qt  = blockIdx.x;
    const int bh  = blockIdx.y;
    const int tid = threadIdx.x;
    const int ty  = tid >> 4;
    const int tx  = tid & 15;

    const float* Qb = g_q + (size_t)bh * HD * SS;   // [d][4096]
    const float* Kb = g_k + (size_t)bh * HD * SS;
    const float* Vb = g_v + (size_t)bh * SS * HD;   // [s][64]

    // Load Q tile (pre-scaled by hd^-0.5) — d-major, contiguous 64-col slabs
#pragma unroll
    for (int i = 0; i < 4; i++) {
        int f = tid + i * 256;
        int d = f >> 4, c4 = (f & 15) * 4;
        float4 t = *(const float4*)&Qb[(size_t)d * SS + qt * 64 + c4];
        t.x *= 0.125f; t.y *= 0.125f; t.z *= 0.125f; t.w *= 0.125f;
        *(float4*)&Qs[d * AST + c4] = t;
    }

    float m[4], l[4], o[4][4];
#pragma unroll
    for (int i = 0; i < 4; i++) {
        m[i] = -1e30f; l[i] = 0.f;
#pragma unroll
        for (int j = 0; j < 4; j++) o[i][j] = 0.f;
    }

    for (int kt = 0; kt <= qt; kt++) {
        __syncthreads();   // prev tile fully consumed (K/V/Ps reusable); Q visible
#pragma unroll
        for (int i = 0; i < 4; i++) {
            int f = tid + i * 256;
            int r = f >> 4, c4 = (f & 15) * 4;
            *(float4*)&Ks[r * AST + c4] =
                *(const float4*)&Kb[(size_t)r * SS + kt * 64 + c4];
            *(float4*)&Vs[r * AST + c4] =
                *(const float4*)&Vb[(size_t)(kt * 64 + r) * HD + c4];
        }
        __syncthreads();

        // S = Q^T K (rank-1 over d)
        float s[4][4] = {};
#pragma unroll 8
        for (int d = 0; d < 64; d++) {
            float4 qv = *(const float4*)&Qs[d * AST + ty * 4];
            float4 kv = *(const float4*)&Ks[d * AST + tx * 4];
            float qr[4] = {qv.x, qv.y, qv.z, qv.w};
            float kr[4] = {kv.x, kv.y, kv.z, kv.w};
#pragma unroll
            for (int i = 0; i < 4; i++)
#pragma unroll
                for (int j = 0; j < 4; j++)
                    s[i][j] += qr[i] * kr[j];
        }

        if (kt == qt) {   // causal mask on diagonal tile
#pragma unroll
            for (int i = 0; i < 4; i++) {
                int grow = qt * 64 + ty * 4 + i;
#pragma unroll
                for (int j = 0; j < 4; j++)
                    if (kt * 64 + tx * 4 + j > grow) s[i][j] = -1e30f;
            }
        }

        // Online softmax per row (16-lane reduction across tx)
#pragma unroll
        for (int i = 0; i < 4; i++) {
            float mt = fmaxf(fmaxf(s[i][0], s[i][1]), fmaxf(s[i][2], s[i][3]));
            mt = fmaxf(mt, __shfl_xor_sync(0xffffffffu, mt, 1));
            mt = fmaxf(mt, __shfl_xor_sync(0xffffffffu, mt, 2));
            mt = fmaxf(mt, __shfl_xor_sync(0xffffffffu, mt, 4));
            mt = fmaxf(mt, __shfl_xor_sync(0xffffffffu, mt, 8));
            float mn = fmaxf(m[i], mt);
            float lt = 0.f;
#pragma unroll
            for (int j = 0; j < 4; j++) {
                s[i][j] = __expf(s[i][j] - mn);
                lt += s[i][j];
            }
            lt += __shfl_xor_sync(0xffffffffu, lt, 1);
            lt += __shfl_xor_sync(0xffffffffu, lt, 2);
            lt += __shfl_xor_sync(0xffffffffu, lt, 4);
            lt += __shfl_xor_sync(0xffffffffu, lt, 8);
            float alpha = __expf(m[i] - mn);
            m[i] = mn;
            l[i] = l[i] * alpha + lt;
#pragma unroll
            for (int j = 0; j < 4; j++) o[i][j] *= alpha;
        }

        // Store P transposed: Ps[c][row]
#pragma unroll
        for (int j = 0; j < 4; j++) {
            float4 pv = make_float4(s[0][j], s[1][j], s[2][j], s[3][j]);
            *(float4*)&Ps[(tx * 4 + j) * AST + ty * 4] = pv;
        }
        __syncthreads();

        // O += P V (rank-1 over c)
#pragma unroll 8
        for (int c = 0; c < 64; c++) {
            float4 pv = *(const float4*)&Ps[c * AST + ty * 4];
            float4 vv = *(const float4*)&Vs[c * AST + tx * 4];
            float pr[4] = {pv.x, pv.y, pv.z, pv.w};
            float vr[4] = {vv.x, vv.y, vv.z, vv.w};
#pragma unroll
            for (int i = 0; i < 4; i++)
#pragma unroll
                for (int j = 0; j < 4; j++)
                    o[i][j] += pr[i] * vr[j];
        }
    }

    // Write O -> g_att [b, s, h*64+d]
    const int b_ = bh / HH, h_ = bh % HH;
#pragma unroll
    for (int i = 0; i < 4; i++) {
        float inv = 1.f / l[i];
        int grow = qt * 64 + ty * 4 + i;
        float4 v = make_float4(o[i][0]*inv, o[i][1]*inv, o[i][2]*inv, o[i][3]*inv);
        *(float4*)&g_att[((size_t)(b_ * SS + grow)) * DD + h_ * HD + tx * 4] = v;
    }
}

// ---------------------------------------------------------------------------
// GEMM2: out = g_att @ Wout + bout. Same 128x128x8 scheme.
// ---------------------------------------------------------------------------
__global__ __launch_bounds__(256, 2) void gemm_out_kernel(
    const float* __restrict__ W, const float* __restrict__ bias,
    float* __restrict__ Y)
{
    __shared__ __align__(16) float As[8][132];
    __shared__ __align__(16) float Bs[8][128];
    const int tid  = threadIdx.x;
    const int col0 = blockIdx.x * 128;
    const int row0 = blockIdx.y * 128;
    const int ty = tid >> 4, tx = tid & 15;

    const int arow = tid >> 1;
    const int ak   = (tid & 1) * 4;
    const int brow = tid >> 5;
    const int bcol = (tid & 31) * 4;

    const float* Ap = g_att + (size_t)(row0 + arow) * DD + ak;
    const float* Bp = W + (size_t)brow * DD + col0 + bcol;

    float4 av = *(const float4*)Ap;
    float4 bv = *(const float4*)Bp;

    float acc[8][8] = {};

    for (int k0 = 0; k0 < DD; k0 += 8) {
        As[ak + 0][arow] = av.x;
        As[ak + 1][arow] = av.y;
        As[ak + 2][arow] = av.z;
        As[ak + 3][arow] = av.w;
        *(float4*)&Bs[brow][bcol] = bv;
        __syncthreads();
        if (k0 + 8 < DD) {
            av = *(const float4*)(Ap + k0 + 8);
            bv = *(const float4*)(Bp + (size_t)(k0 + 8) * DD);
        }
#pragma unroll
        for (int kk = 0; kk < 8; kk++) {
            float4 a0 = *(const float4*)&As[kk][ty * 4];
            float4 a1 = *(const float4*)&As[kk][64 + ty * 4];
            float4 b0 = *(const float4*)&Bs[kk][tx * 4];
            float4 b1 = *(const float4*)&Bs[kk][64 + tx * 4];
            float ar[8] = {a0.x,a0.y,a0.z,a0.w,a1.x,a1.y,a1.z,a1.w};
            float br[8] = {b0.x,b0.y,b0.z,b0.w,b1.x,b1.y,b1.z,b1.w};
#pragma unroll
            for (int i = 0; i < 8; i++)
#pragma unroll
                for (int j = 0; j < 8; j++)
                    acc[i][j] += ar[i] * br[j];
        }
        __syncthreads();
    }

#pragma unroll
    for (int g = 0; g < 2; g++) {
        float4 bb = *(const float4*)&bias[col0 + g * 64 + tx * 4];
#pragma unroll
        for (int i = 0; i < 8; i++) {
            int r = row0 + ((i < 4) ? ty * 4 + i : 64 + ty * 4 + i - 4);
            float4 v;
            v.x = acc[i][g*4+0] + bb.x;
            v.y = acc[i][g*4+1] + bb.y;
            v.z = acc[i][g*4+2] + bb.z;
            v.w = acc[i][g*4+3] + bb.w;
            *(float4*)&Y[(size_t)r * DD + col0 + g * 64 + tx * 4] = v;
        }
    }
}

// ---------------------------------------------------------------------------
extern "C" void kernel_launch(void* const* d_in, const int* in_sizes, int n_in,
                              void* d_out, int out_size)
{
    const float* x    = (const float*)d_in[0];
    const float* Wqkv = (const float*)d_in[1];
    const float* bqkv = (const float*)d_in[2];
    const float* Wout = (const float*)d_in[3];
    const float* bout = (const float*)d_in[4];
    float* out = (float*)d_out;

    cudaFuncSetAttribute(attn_kernel,
                         cudaFuncAttributeMaxDynamicSharedMemorySize, ATTN_SMEM);

    gemm_qkv_kernel<<<dim3(N3 / 128, MM / 128), 256>>>(x, Wqkv, bqkv);
    attn_kernel<<<dim3(SS / 64, BB * HH), 256, ATTN_SMEM>>>();
    gemm_out_kernel<<<dim3(DD / 128, MM / 128), 256>>>(Wout, bout, out);
}

// round 5
// speedup vs baseline: 2.9411x; 1.8511x over previous
#include <cuda_runtime.h>
#include <cuda_bf16.h>
#include <cstdint>

#define BB 2
#define SS 4096
#define DD 768
#define HH 12
#define HD 64
#define N3 (3*DD)
#define MM (BB*SS)

// Scratch. Q,K d-major [b,h,d,s]; V row-major [b,h,s,d]
__device__ __align__(16) float g_q[BB*HH*HD*SS];
__device__ __align__(16) float g_k[BB*HH*HD*SS];
__device__ __align__(16) float g_v[BB*HH*SS*HD];
__device__ __align__(16) float g_att[MM*DD];
// bf16 hi/lo split operands
__device__ __align__(16) __nv_bfloat16 g_xh[MM*DD],  g_xl[MM*DD];
__device__ __align__(16) __nv_bfloat16 g_oh[MM*DD],  g_ol[MM*DD];
__device__ __align__(16) __nv_bfloat16 g_w1h[N3*DD], g_w1l[N3*DD];
__device__ __align__(16) __nv_bfloat16 g_w2h[DD*DD], g_w2l[DD*DD];

// ---------------- helpers ----------------
__device__ __forceinline__ uint32_t smem_u32(const void* p) {
    uint32_t a;
    asm("{ .reg .u64 t; cvta.to.shared.u64 t, %1; cvt.u32.u64 %0, t; }" : "=r"(a) : "l"(p));
    return a;
}
__device__ __forceinline__ void ldsm4(uint32_t* r, uint32_t addr) {
    asm volatile("ldmatrix.sync.aligned.m8n8.x4.shared.b16 {%0,%1,%2,%3}, [%4];"
        : "=r"(r[0]), "=r"(r[1]), "=r"(r[2]), "=r"(r[3]) : "r"(addr));
}
__device__ __forceinline__ void mma16816(float* c, const uint32_t* a, const uint32_t* b) {
    asm volatile(
        "mma.sync.aligned.m16n8k16.row.col.f32.bf16.bf16.f32 "
        "{%0,%1,%2,%3}, {%4,%5,%6,%7}, {%8,%9}, {%0,%1,%2,%3};"
        : "+f"(c[0]), "+f"(c[1]), "+f"(c[2]), "+f"(c[3])
        : "r"(a[0]), "r"(a[1]), "r"(a[2]), "r"(a[3]), "r"(b[0]), "r"(b[1]));
}

// smem layout (bytes). Tile rows: 32 bf16 + 8 pad = 40 bf16 = 80 B stride.
#define TROW 80
#define OFF_AH 0
#define OFF_AL (OFF_AH + 128*TROW)
#define OFF_BH (OFF_AL + 128*TROW)
#define OFF_BL (OFF_BH + 128*TROW)
#define OFF_BIAS (OFF_BL + 128*TROW)          // 40960
#define GEMM_SMEM (OFF_BIAS + 512)            // 41472
#define NCHUNK (DD/32)                        // 24

// ---------------------------------------------------------------------------
// split: fp32 -> bf16 hi/lo (elementwise)
// ---------------------------------------------------------------------------
__global__ __launch_bounds__(256) void split_kernel(
    const float* __restrict__ src, __nv_bfloat16* __restrict__ hi,
    __nv_bfloat16* __restrict__ lo)
{
    int i = (blockIdx.x * 256 + threadIdx.x) * 4;
    float4 v = *(const float4*)(src + i);
    __nv_bfloat16 h0 = __float2bfloat16(v.x), h1 = __float2bfloat16(v.y);
    __nv_bfloat16 h2 = __float2bfloat16(v.z), h3 = __float2bfloat16(v.w);
    __nv_bfloat16 l0 = __float2bfloat16(v.x - __bfloat162float(h0));
    __nv_bfloat16 l1 = __float2bfloat16(v.y - __bfloat162float(h1));
    __nv_bfloat16 l2 = __float2bfloat16(v.z - __bfloat162float(h2));
    __nv_bfloat16 l3 = __float2bfloat16(v.w - __bfloat162float(h3));
    *(__nv_bfloat162*)(hi + i)     = __nv_bfloat162(h0, h1);
    *(__nv_bfloat162*)(hi + i + 2) = __nv_bfloat162(h2, h3);
    *(__nv_bfloat162*)(lo + i)     = __nv_bfloat162(l0, l1);
    *(__nv_bfloat162*)(lo + i + 2) = __nv_bfloat162(l2, l3);
}

// ---------------------------------------------------------------------------
// transpose + split: dst[c][r] = src[r][c] as bf16 hi/lo
// ---------------------------------------------------------------------------
__global__ void transpose_split_kernel(
    const float* __restrict__ src, __nv_bfloat16* __restrict__ hi,
    __nv_bfloat16* __restrict__ lo, int R, int C)
{
    __shared__ float t[32][33];
    int bx = blockIdx.x * 32, by = blockIdx.y * 32;
    int tx = threadIdx.x, ty = threadIdx.y;
#pragma unroll
    for (int i = 0; i < 32; i += 8)
        t[ty + i][tx] = src[(size_t)(by + ty + i) * C + bx + tx];
    __syncthreads();
#pragma unroll
    for (int i = 0; i < 32; i += 8) {
        float v = t[tx][ty + i];
        __nv_bfloat16 h = __float2bfloat16(v);
        __nv_bfloat16 l = __float2bfloat16(v - __bfloat162float(h));
        size_t o = (size_t)(bx + ty + i) * R + by + tx;
        hi[o] = h; lo[o] = l;
    }
}

// ---------------------------------------------------------------------------
// bf16x3 MMA mainloop: C(128x128) = A(row0..+127, K=768) * B(col0..+127, K)^T
// A,B given as bf16 hi/lo row-major [*][768]. Result in c[4][4][4] per thread.
// Warp w = (wr = w>>2)*64 rows, (wc = w&3)*32 cols.
// ---------------------------------------------------------------------------
__device__ __forceinline__ void gemm_mainloop(
    const __nv_bfloat16* __restrict__ Ah, const __nv_bfloat16* __restrict__ Al,
    const __nv_bfloat16* __restrict__ Bh, const __nv_bfloat16* __restrict__ Bl,
    const float* __restrict__ bias_g,
    char* sm, uint32_t smb, int row0, int col0, float c[4][4][4])
{
    const int tid  = threadIdx.x;
    const int wid  = tid >> 5, lane = tid & 31;
    const int wr   = wid >> 2, wc = wid & 3;
    const int arow = tid >> 1;
    const int ak   = (tid & 1) * 16;

    if (tid < 128) ((float*)(sm + OFF_BIAS))[tid] = bias_g[col0 + tid];

    const size_t aoff = (size_t)(row0 + arow) * DD + ak;
    const size_t boff = (size_t)(col0 + arow) * DD + ak;
    const uint32_t sts = (uint32_t)(arow * TROW + ak * 2);

    uint4 pa[4], pb[4];
    {
        pa[0] = *(const uint4*)(Ah + aoff);     pa[1] = *(const uint4*)(Ah + aoff + 8);
        pa[2] = *(const uint4*)(Al + aoff);     pa[3] = *(const uint4*)(Al + aoff + 8);
        pb[0] = *(const uint4*)(Bh + boff);     pb[1] = *(const uint4*)(Bh + boff + 8);
        pb[2] = *(const uint4*)(Bl + boff);     pb[3] = *(const uint4*)(Bl + boff + 8);
    }

    // ldmatrix lane address pieces
    const int lrow = lane & 15;           // row within 16-row block
    const int lk   = (lane >> 4) * 8;     // k sub-column (0 or 8)

    for (int ch = 0; ch < NCHUNK; ch++) {
        __syncthreads();
        *(uint4*)(sm + OFF_AH + sts)      = pa[0];
        *(uint4*)(sm + OFF_AH + sts + 16) = pa[1];
        *(uint4*)(sm + OFF_AL + sts)      = pa[2];
        *(uint4*)(sm + OFF_AL + sts + 16) = pa[3];
        *(uint4*)(sm + OFF_BH + sts)      = pb[0];
        *(uint4*)(sm + OFF_BH + sts + 16) = pb[1];
        *(uint4*)(sm + OFF_BL + sts)      = pb[2];
        *(uint4*)(sm + OFF_BL + sts + 16) = pb[3];
        __syncthreads();

        if (ch + 1 < NCHUNK) {
            const int k1 = (ch + 1) * 32;
            pa[0] = *(const uint4*)(Ah + aoff + k1); pa[1] = *(const uint4*)(Ah + aoff + k1 + 8);
            pa[2] = *(const uint4*)(Al + aoff + k1); pa[3] = *(const uint4*)(Al + aoff + k1 + 8);
            pb[0] = *(const uint4*)(Bh + boff + k1); pb[1] = *(const uint4*)(Bh + boff + k1 + 8);
            pb[2] = *(const uint4*)(Bl + boff + k1); pb[3] = *(const uint4*)(Bl + boff + k1 + 8);
        }

#pragma unroll
        for (int ks = 0; ks < 2; ks++) {
            const uint32_t kb = (uint32_t)((ks * 16 + lk) * 2);
            uint32_t a_hi[4][4], a_lo[4][4], b_hi[4][2], b_lo[4][2];
#pragma unroll
            for (int mt = 0; mt < 4; mt++) {
                uint32_t ra = smb + (uint32_t)((wr * 64 + mt * 16 + lrow) * TROW) + kb;
                ldsm4(a_hi[mt], OFF_AH + ra);
                ldsm4(a_lo[mt], OFF_AL + ra);
            }
#pragma unroll
            for (int g = 0; g < 2; g++) {
                uint32_t rb = smb + (uint32_t)((wc * 32 + g * 16 + lrow) * TROW) + kb;
                uint32_t r[4];
                ldsm4(r, OFF_BH + rb);
                b_hi[2*g][0] = r[0]; b_hi[2*g][1] = r[2];
                b_hi[2*g+1][0] = r[1]; b_hi[2*g+1][1] = r[3];
                ldsm4(r, OFF_BL + rb);
                b_lo[2*g][0] = r[0]; b_lo[2*g][1] = r[2];
                b_lo[2*g+1][0] = r[1]; b_lo[2*g+1][1] = r[3];
            }
#pragma unroll
            for (int mt = 0; mt < 4; mt++)
#pragma unroll
                for (int nt = 0; nt < 4; nt++) {
                    mma16816(c[mt][nt], a_hi[mt], b_hi[nt]);
                    mma16816(c[mt][nt], a_hi[mt], b_lo[nt]);
                    mma16816(c[mt][nt], a_lo[mt], b_hi[nt]);
                }
        }
    }
    __syncthreads();
}

// ---------------------------------------------------------------------------
// GEMM1: qkv projection with Q/K d-major scatter, V row-major
// ---------------------------------------------------------------------------
__global__ __launch_bounds__(256) void gemm_qkv_tc(const float* __restrict__ bqkv)
{
    extern __shared__ char sm[];
    const uint32_t smb = smem_u32(sm);
    const int col0 = blockIdx.x * 128;     // in [0, 2304)
    const int row0 = blockIdx.y * 128;
    const int tid = threadIdx.x, wid = tid >> 5, lane = tid & 31;
    const int wr = wid >> 2, wc = wid & 3;

    float c[4][4][4] = {};
    gemm_mainloop(g_xh, g_xl, g_w1h, g_w1l, bqkv, sm, smb, row0, col0, c);

    const float* bias_s = (const float*)(sm + OFF_BIAS);
    const int which = col0 / DD;
    const int h0 = (col0 % DD) / HD;
    const int b_ = row0 >> 12;
    const int s0 = row0 & 4095;

    if (which == 2) {
        const int h = h0 + (wc >> 1);
        float* vb = g_v + (size_t)(b_ * HH + h) * SS * HD;
#pragma unroll
        for (int mt = 0; mt < 4; mt++)
#pragma unroll
            for (int nt = 0; nt < 4; nt++) {
                int d  = (wc & 1) * 32 + nt * 8 + (lane & 3) * 2;
                float bx = bias_s[(wc >> 1) * 64 + d];
                float by = bias_s[(wc >> 1) * 64 + d + 1];
#pragma unroll
                for (int hh = 0; hh < 2; hh++) {
                    int gs = s0 + wr * 64 + mt * 16 + (lane >> 2) + hh * 8;
                    float2 v = make_float2(c[mt][nt][2*hh] + bx, c[mt][nt][2*hh+1] + by);
                    *(float2*)&vb[(size_t)gs * HD + d] = v;
                }
            }
    } else {
        float* qk = (which == 0) ? g_q : g_k;
        float* tbuf = (float*)sm;   // [64][132] reuses tile smem
#pragma unroll
        for (int ph = 0; ph < 2; ph++) {
            if ((wc >> 1) == ph) {
#pragma unroll
                for (int mt = 0; mt < 4; mt++)
#pragma unroll
                    for (int nt = 0; nt < 4; nt++) {
                        int d = (wc & 1) * 32 + nt * 8 + (lane & 3) * 2;
#pragma unroll
                        for (int hh = 0; hh < 2; hh++) {
                            int row = wr * 64 + mt * 16 + (lane >> 2) + hh * 8;
                            tbuf[d * 132 + row]       = c[mt][nt][2*hh]   + bias_s[ph*64 + d];
                            tbuf[(d+1) * 132 + row]   = c[mt][nt][2*hh+1] + bias_s[ph*64 + d + 1];
                        }
                    }
            }
            __syncthreads();
            const int h = h0 + ph;
            const int d = tid >> 2;
            const int s4 = (tid & 3) * 32;
            float* dst = qk + ((size_t)(b_ * HH + h) * HD + d) * SS + s0;
#pragma unroll
            for (int i = 0; i < 8; i++)
                *(float4*)&dst[s4 + 4*i] = *(const float4*)&tbuf[d * 132 + s4 + 4*i];
            __syncthreads();
        }
    }
}

// ---------------------------------------------------------------------------
// GEMM2: out projection
// ---------------------------------------------------------------------------
__global__ __launch_bounds__(256) void gemm_out_tc(const float* __restrict__ bout,
                                                   float* __restrict__ Y)
{
    extern __shared__ char sm[];
    const uint32_t smb = smem_u32(sm);
    const int col0 = blockIdx.x * 128;
    const int row0 = blockIdx.y * 128;
    const int tid = threadIdx.x, wid = tid >> 5, lane = tid & 31;
    const int wr = wid >> 2, wc = wid & 3;

    float c[4][4][4] = {};
    gemm_mainloop(g_oh, g_ol, g_w2h, g_w2l, bout, sm, smb, row0, col0, c);

    const float* bias_s = (const float*)(sm + OFF_BIAS);
#pragma unroll
    for (int mt = 0; mt < 4; mt++)
#pragma unroll
        for (int nt = 0; nt < 4; nt++) {
            int cl = wc * 32 + nt * 8 + (lane & 3) * 2;
            float bx = bias_s[cl], by = bias_s[cl + 1];
#pragma unroll
            for (int hh = 0; hh < 2; hh++) {
                int r = row0 + wr * 64 + mt * 16 + (lane >> 2) + hh * 8;
                float2 v = make_float2(c[mt][nt][2*hh] + bx, c[mt][nt][2*hh+1] + by);
                *(float2*)&Y[(size_t)r * DD + col0 + cl] = v;   // FIXED: + col0
            }
        }
}

// ---------------------------------------------------------------------------
// Flash attention (round-2 proven version, SIMT fp32, Q/K d-major)
// Heavy CTAs (large qt) scheduled first via reversed blockIdx mapping.
// ---------------------------------------------------------------------------
#define AST 68
#define ATTN_SMEM (4 * 64 * AST * 4)

__global__ __launch_bounds__(256, 2) void attn_kernel()
{
    extern __shared__ float smf[];
    float* Qs = smf;
    float* Ks = smf + 64 * AST;
    float* Vs = smf + 2 * 64 * AST;
    float* Ps = smf + 3 * 64 * AST;

    const int qt  = gridDim.x - 1 - blockIdx.x;   // heavy tiles first
    const int bh  = blockIdx.y;
    const int tid = threadIdx.x;
    const int ty  = tid >> 4;
    const int tx  = tid & 15;

    const float* Qb = g_q + (size_t)bh * HD * SS;
    const float* Kb = g_k + (size_t)bh * HD * SS;
    const float* Vb = g_v + (size_t)bh * SS * HD;

#pragma unroll
    for (int i = 0; i < 4; i++) {
        int f = tid + i * 256;
        int d = f >> 4, c4 = (f & 15) * 4;
        float4 t = *(const float4*)&Qb[(size_t)d * SS + qt * 64 + c4];
        t.x *= 0.125f; t.y *= 0.125f; t.z *= 0.125f; t.w *= 0.125f;
        *(float4*)&Qs[d * AST + c4] = t;
    }

    float m[4], l[4], o[4][4];
#pragma unroll
    for (int i = 0; i < 4; i++) {
        m[i] = -1e30f; l[i] = 0.f;
#pragma unroll
        for (int j = 0; j < 4; j++) o[i][j] = 0.f;
    }

    for (int kt = 0; kt <= qt; kt++) {
        __syncthreads();
#pragma unroll
        for (int i = 0; i < 4; i++) {
            int f = tid + i * 256;
            int r = f >> 4, c4 = (f & 15) * 4;
            *(float4*)&Ks[r * AST + c4] =
                *(const float4*)&Kb[(size_t)r * SS + kt * 64 + c4];
            *(float4*)&Vs[r * AST + c4] =
                *(const float4*)&Vb[(size_t)(kt * 64 + r) * HD + c4];
        }
        __syncthreads();

        float s[4][4] = {};
#pragma unroll 8
        for (int d = 0; d < 64; d++) {
            float4 qv = *(const float4*)&Qs[d * AST + ty * 4];
            float4 kv = *(const float4*)&Ks[d * AST + tx * 4];
            float qr[4] = {qv.x, qv.y, qv.z, qv.w};
            float kr[4] = {kv.x, kv.y, kv.z, kv.w};
#pragma unroll
            for (int i = 0; i < 4; i++)
#pragma unroll
                for (int j = 0; j < 4; j++)
                    s[i][j] += qr[i] * kr[j];
        }

        if (kt == qt) {
#pragma unroll
            for (int i = 0; i < 4; i++) {
                int grow = qt * 64 + ty * 4 + i;
#pragma unroll
                for (int j = 0; j < 4; j++)
                    if (kt * 64 + tx * 4 + j > grow) s[i][j] = -1e30f;
            }
        }

#pragma unroll
        for (int i = 0; i < 4; i++) {
            float mt = fmaxf(fmaxf(s[i][0], s[i][1]), fmaxf(s[i][2], s[i][3]));
            mt = fmaxf(mt, __shfl_xor_sync(0xffffffffu, mt, 1));
            mt = fmaxf(mt, __shfl_xor_sync(0xffffffffu, mt, 2));
            mt = fmaxf(mt, __shfl_xor_sync(0xffffffffu, mt, 4));
            mt = fmaxf(mt, __shfl_xor_sync(0xffffffffu, mt, 8));
            float mn = fmaxf(m[i], mt);
            float lt = 0.f;
#pragma unroll
            for (int j = 0; j < 4; j++) {
                s[i][j] = __expf(s[i][j] - mn);
                lt += s[i][j];
            }
            lt += __shfl_xor_sync(0xffffffffu, lt, 1);
            lt += __shfl_xor_sync(0xffffffffu, lt, 2);
            lt += __shfl_xor_sync(0xffffffffu, lt, 4);
            lt += __shfl_xor_sync(0xffffffffu, lt, 8);
            float alpha = __expf(m[i] - mn);
            m[i] = mn;
            l[i] = l[i] * alpha + lt;
#pragma unroll
            for (int j = 0; j < 4; j++) o[i][j] *= alpha;
        }

#pragma unroll
        for (int j = 0; j < 4; j++) {
            float4 pv = make_float4(s[0][j], s[1][j], s[2][j], s[3][j]);
            *(float4*)&Ps[(tx * 4 + j) * AST + ty * 4] = pv;
        }
        __syncthreads();

#pragma unroll 8
        for (int cc = 0; cc < 64; cc++) {
            float4 pv = *(const float4*)&Ps[cc * AST + ty * 4];
            float4 vv = *(const float4*)&Vs[cc * AST + tx * 4];
            float pr[4] = {pv.x, pv.y, pv.z, pv.w};
            float vr[4] = {vv.x, vv.y, vv.z, vv.w};
#pragma unroll
            for (int i = 0; i < 4; i++)
#pragma unroll
                for (int j = 0; j < 4; j++)
                    o[i][j] += pr[i] * vr[j];
        }
    }

    const int b_ = bh / HH, h_ = bh % HH;
#pragma unroll
    for (int i = 0; i < 4; i++) {
        float inv = 1.f / l[i];
        int grow = qt * 64 + ty * 4 + i;
        float4 v = make_float4(o[i][0]*inv, o[i][1]*inv, o[i][2]*inv, o[i][3]*inv);
        *(float4*)&g_att[((size_t)(b_ * SS + grow)) * DD + h_ * HD + tx * 4] = v;
    }
}

// ---------------------------------------------------------------------------
extern "C" void kernel_launch(void* const* d_in, const int* in_sizes, int n_in,
                              void* d_out, int out_size)
{
    const float* x    = (const float*)d_in[0];
    const float* Wqkv = (const float*)d_in[1];
    const float* bqkv = (const float*)d_in[2];
    const float* Wout = (const float*)d_in[3];
    const float* bout = (const float*)d_in[4];
    float* out = (float*)d_out;

    cudaFuncSetAttribute(attn_kernel, cudaFuncAttributeMaxDynamicSharedMemorySize, ATTN_SMEM);

    __nv_bfloat16 *xh, *xl, *oh, *ol, *w1h, *w1l, *w2h, *w2l;
    float* att;
    cudaGetSymbolAddress((void**)&xh,  g_xh);  cudaGetSymbolAddress((void**)&xl,  g_xl);
    cudaGetSymbolAddress((void**)&oh,  g_oh);  cudaGetSymbolAddress((void**)&ol,  g_ol);
    cudaGetSymbolAddress((void**)&w1h, g_w1h); cudaGetSymbolAddress((void**)&w1l, g_w1l);
    cudaGetSymbolAddress((void**)&w2h, g_w2h); cudaGetSymbolAddress((void**)&w2l, g_w2l);
    cudaGetSymbolAddress((void**)&att, g_att);

    split_kernel<<<MM * DD / 1024, 256>>>(x, xh, xl);
    transpose_split_kernel<<<dim3(N3 / 32, DD / 32), dim3(32, 8)>>>(Wqkv, w1h, w1l, DD, N3);
    transpose_split_kernel<<<dim3(DD / 32, DD / 32), dim3(32, 8)>>>(Wout, w2h, w2l, DD, DD);

    gemm_qkv_tc<<<dim3(N3 / 128, MM / 128), 256, GEMM_SMEM>>>(bqkv);
    attn_kernel<<<dim3(SS / 64, BB * HH), 256, ATTN_SMEM>>>();

    split_kernel<<<MM * DD / 1024, 256>>>(att, oh, ol);
    gemm_out_tc<<<dim3(DD / 128, MM / 128), 256, GEMM_SMEM>>>(bout, out);
}

// round 6
// speedup vs baseline: 6.0793x; 2.0670x over previous
#include <cuda_runtime.h>
#include <cuda_bf16.h>
#include <cstdint>

#define BB 2
#define SS 4096
#define DD 768
#define HH 12
#define HD 64
#define N3 (3*DD)
#define MM (BB*SS)

// bf16 hi/lo scratch
__device__ __align__(16) __nv_bfloat16 g_qh[BB*HH*SS*HD], g_ql[BB*HH*SS*HD];
__device__ __align__(16) __nv_bfloat16 g_kh[BB*HH*SS*HD], g_kl[BB*HH*SS*HD];
__device__ __align__(16) __nv_bfloat16 g_vh[BB*HH*SS*HD], g_vl[BB*HH*SS*HD];
__device__ __align__(16) __nv_bfloat16 g_oh[MM*DD],  g_ol[MM*DD];
__device__ __align__(16) __nv_bfloat16 g_xh[MM*DD],  g_xl[MM*DD];
__device__ __align__(16) __nv_bfloat16 g_w1h[N3*DD], g_w1l[N3*DD];
__device__ __align__(16) __nv_bfloat16 g_w2h[DD*DD], g_w2l[DD*DD];

// ---------------- helpers ----------------
__device__ __forceinline__ uint32_t smem_u32(const void* p) {
    uint32_t a;
    asm("{ .reg .u64 t; cvta.to.shared.u64 t, %1; cvt.u32.u64 %0, t; }" : "=r"(a) : "l"(p));
    return a;
}
__device__ __forceinline__ void ldsm4(uint32_t* r, uint32_t addr) {
    asm volatile("ldmatrix.sync.aligned.m8n8.x4.shared.b16 {%0,%1,%2,%3}, [%4];"
        : "=r"(r[0]), "=r"(r[1]), "=r"(r[2]), "=r"(r[3]) : "r"(addr));
}
__device__ __forceinline__ void ldsm4t(uint32_t* r, uint32_t addr) {
    asm volatile("ldmatrix.sync.aligned.m8n8.x4.trans.shared.b16 {%0,%1,%2,%3}, [%4];"
        : "=r"(r[0]), "=r"(r[1]), "=r"(r[2]), "=r"(r[3]) : "r"(addr));
}
__device__ __forceinline__ void mma16816(float* c, const uint32_t* a, const uint32_t* b) {
    asm volatile(
        "mma.sync.aligned.m16n8k16.row.col.f32.bf16.bf16.f32 "
        "{%0,%1,%2,%3}, {%4,%5,%6,%7}, {%8,%9}, {%0,%1,%2,%3};"
        : "+f"(c[0]), "+f"(c[1]), "+f"(c[2]), "+f"(c[3])
        : "r"(a[0]), "r"(a[1]), "r"(a[2]), "r"(a[3]), "r"(b[0]), "r"(b[1]));
}
__device__ __forceinline__ uint32_t packbf(float x, float y) {
    __nv_bfloat162 h = __floats2bfloat162_rn(x, y);
    return *(uint32_t*)&h;
}
__device__ __forceinline__ void split2(float x, float y, uint32_t& h, uint32_t& l) {
    __nv_bfloat16 hx = __float2bfloat16(x), hy = __float2bfloat16(y);
    h = packbf(x, y);
    l = packbf(x - __bfloat162float(hx), y - __bfloat162float(hy));
}

// ---------------- GEMM smem layout ----------------
#define TROW 80
#define OFF_AH 0
#define OFF_AL (OFF_AH + 128*TROW)
#define OFF_BH (OFF_AL + 128*TROW)
#define OFF_BL (OFF_BH + 128*TROW)
#define OFF_BIAS (OFF_BL + 128*TROW)
#define GEMM_SMEM (OFF_BIAS + 512)
#define NCHUNK (DD/32)

// ---------------------------------------------------------------------------
__global__ __launch_bounds__(256) void split_kernel(
    const float* __restrict__ src, __nv_bfloat16* __restrict__ hi,
    __nv_bfloat16* __restrict__ lo)
{
    int i = (blockIdx.x * 256 + threadIdx.x) * 4;
    float4 v = *(const float4*)(src + i);
    uint32_t h0, l0, h1, l1;
    split2(v.x, v.y, h0, l0);
    split2(v.z, v.w, h1, l1);
    *(uint32_t*)(hi + i) = h0; *(uint32_t*)(hi + i + 2) = h1;
    *(uint32_t*)(lo + i) = l0; *(uint32_t*)(lo + i + 2) = l1;
}

__global__ void transpose_split_kernel(
    const float* __restrict__ src, __nv_bfloat16* __restrict__ hi,
    __nv_bfloat16* __restrict__ lo, int R, int C)
{
    __shared__ float t[32][33];
    int bx = blockIdx.x * 32, by = blockIdx.y * 32;
    int tx = threadIdx.x, ty = threadIdx.y;
#pragma unroll
    for (int i = 0; i < 32; i += 8)
        t[ty + i][tx] = src[(size_t)(by + ty + i) * C + bx + tx];
    __syncthreads();
#pragma unroll
    for (int i = 0; i < 32; i += 8) {
        float v = t[tx][ty + i];
        __nv_bfloat16 h = __float2bfloat16(v);
        size_t o = (size_t)(bx + ty + i) * R + by + tx;
        hi[o] = h; lo[o] = __float2bfloat16(v - __bfloat162float(h));
    }
}

// ---------------------------------------------------------------------------
// bf16x3 MMA mainloop (unchanged, proven)
// ---------------------------------------------------------------------------
__device__ __forceinline__ void gemm_mainloop(
    const __nv_bfloat16* __restrict__ Ah, const __nv_bfloat16* __restrict__ Al,
    const __nv_bfloat16* __restrict__ Bh, const __nv_bfloat16* __restrict__ Bl,
    const float* __restrict__ bias_g,
    char* sm, uint32_t smb, int row0, int col0, float c[4][4][4])
{
    const int tid  = threadIdx.x;
    const int wid  = tid >> 5, lane = tid & 31;
    const int wr   = wid >> 2, wc = wid & 3;
    const int arow = tid >> 1;
    const int ak   = (tid & 1) * 16;

    if (tid < 128) ((float*)(sm + OFF_BIAS))[tid] = bias_g[col0 + tid];

    const size_t aoff = (size_t)(row0 + arow) * DD + ak;
    const size_t boff = (size_t)(col0 + arow) * DD + ak;
    const uint32_t sts = (uint32_t)(arow * TROW + ak * 2);

    uint4 pa[4], pb[4];
    pa[0] = *(const uint4*)(Ah + aoff); pa[1] = *(const uint4*)(Ah + aoff + 8);
    pa[2] = *(const uint4*)(Al + aoff); pa[3] = *(const uint4*)(Al + aoff + 8);
    pb[0] = *(const uint4*)(Bh + boff); pb[1] = *(const uint4*)(Bh + boff + 8);
    pb[2] = *(const uint4*)(Bl + boff); pb[3] = *(const uint4*)(Bl + boff + 8);

    const int lrow = lane & 15;
    const int lk   = (lane >> 4) * 8;

    for (int ch = 0; ch < NCHUNK; ch++) {
        __syncthreads();
        *(uint4*)(sm + OFF_AH + sts)      = pa[0];
        *(uint4*)(sm + OFF_AH + sts + 16) = pa[1];
        *(uint4*)(sm + OFF_AL + sts)      = pa[2];
        *(uint4*)(sm + OFF_AL + sts + 16) = pa[3];
        *(uint4*)(sm + OFF_BH + sts)      = pb[0];
        *(uint4*)(sm + OFF_BH + sts + 16) = pb[1];
        *(uint4*)(sm + OFF_BL + sts)      = pb[2];
        *(uint4*)(sm + OFF_BL + sts + 16) = pb[3];
        __syncthreads();

        if (ch + 1 < NCHUNK) {
            const int k1 = (ch + 1) * 32;
            pa[0] = *(const uint4*)(Ah + aoff + k1); pa[1] = *(const uint4*)(Ah + aoff + k1 + 8);
            pa[2] = *(const uint4*)(Al + aoff + k1); pa[3] = *(const uint4*)(Al + aoff + k1 + 8);
            pb[0] = *(const uint4*)(Bh + boff + k1); pb[1] = *(const uint4*)(Bh + boff + k1 + 8);
            pb[2] = *(const uint4*)(Bl + boff + k1); pb[3] = *(const uint4*)(Bl + boff + k1 + 8);
        }

#pragma unroll
        for (int ks = 0; ks < 2; ks++) {
            const uint32_t kb = (uint32_t)((ks * 16 + lk) * 2);
            uint32_t a_hi[4][4], a_lo[4][4], b_hi[4][2], b_lo[4][2];
#pragma unroll
            for (int mt = 0; mt < 4; mt++) {
                uint32_t ra = smb + (uint32_t)((wr * 64 + mt * 16 + lrow) * TROW) + kb;
                ldsm4(a_hi[mt], OFF_AH + ra);
                ldsm4(a_lo[mt], OFF_AL + ra);
            }
#pragma unroll
            for (int g = 0; g < 2; g++) {
                uint32_t rb = smb + (uint32_t)((wc * 32 + g * 16 + lrow) * TROW) + kb;
                uint32_t r[4];
                ldsm4(r, OFF_BH + rb);
                b_hi[2*g][0] = r[0]; b_hi[2*g][1] = r[2];
                b_hi[2*g+1][0] = r[1]; b_hi[2*g+1][1] = r[3];
                ldsm4(r, OFF_BL + rb);
                b_lo[2*g][0] = r[0]; b_lo[2*g][1] = r[2];
                b_lo[2*g+1][0] = r[1]; b_lo[2*g+1][1] = r[3];
            }
#pragma unroll
            for (int mt = 0; mt < 4; mt++)
#pragma unroll
                for (int nt = 0; nt < 4; nt++) {
                    mma16816(c[mt][nt], a_hi[mt], b_hi[nt]);
                    mma16816(c[mt][nt], a_hi[mt], b_lo[nt]);
                    mma16816(c[mt][nt], a_lo[mt], b_hi[nt]);
                }
        }
    }
    __syncthreads();
}

// ---------------------------------------------------------------------------
// GEMM1: qkv projection -> bf16 hi/lo Q(scaled)/K/V in [b,h,s,d]
// ---------------------------------------------------------------------------
__global__ __launch_bounds__(256) void gemm_qkv_tc(const float* __restrict__ bqkv)
{
    extern __shared__ char sm[];
    const uint32_t smb = smem_u32(sm);
    const int col0 = blockIdx.x * 128;
    const int row0 = blockIdx.y * 128;
    const int tid = threadIdx.x, wid = tid >> 5, lane = tid & 31;
    const int wr = wid >> 2, wc = wid & 3;

    float c[4][4][4] = {};
    gemm_mainloop(g_xh, g_xl, g_w1h, g_w1l, bqkv, sm, smb, row0, col0, c);

    const float* bias_s = (const float*)(sm + OFF_BIAS);
    const int which = col0 / DD;
    const int h = (col0 % DD) / HD + (wc >> 1);
    const int b_ = row0 >> 12;
    const int s0 = row0 & 4095;
    const float scale = (which == 0) ? 0.125f : 1.0f;

    __nv_bfloat16* dh = (which == 0) ? g_qh : (which == 1) ? g_kh : g_vh;
    __nv_bfloat16* dl = (which == 0) ? g_ql : (which == 1) ? g_kl : g_vl;
    const size_t base = (size_t)(b_ * HH + h) * SS * HD;

#pragma unroll
    for (int mt = 0; mt < 4; mt++)
#pragma unroll
        for (int nt = 0; nt < 4; nt++) {
            int d = (wc & 1) * 32 + nt * 8 + (lane & 3) * 2;
            float bx = bias_s[(wc >> 1) * 64 + d];
            float by = bias_s[(wc >> 1) * 64 + d + 1];
#pragma unroll
            for (int hh = 0; hh < 2; hh++) {
                int gs = s0 + wr * 64 + mt * 16 + (lane >> 2) + hh * 8;
                float v0 = (c[mt][nt][2*hh]   + bx) * scale;
                float v1 = (c[mt][nt][2*hh+1] + by) * scale;
                uint32_t hp, lp;
                split2(v0, v1, hp, lp);
                *(uint32_t*)&dh[base + (size_t)gs * HD + d] = hp;
                *(uint32_t*)&dl[base + (size_t)gs * HD + d] = lp;
            }
        }
}

// ---------------------------------------------------------------------------
// GEMM2: out projection (A = attention output hi/lo)
// ---------------------------------------------------------------------------
__global__ __launch_bounds__(256) void gemm_out_tc(const float* __restrict__ bout,
                                                   float* __restrict__ Y)
{
    extern __shared__ char sm[];
    const uint32_t smb = smem_u32(sm);
    const int col0 = blockIdx.x * 128;
    const int row0 = blockIdx.y * 128;
    const int tid = threadIdx.x, wid = tid >> 5, lane = tid & 31;
    const int wr = wid >> 2, wc = wid & 3;

    float c[4][4][4] = {};
    gemm_mainloop(g_oh, g_ol, g_w2h, g_w2l, bout, sm, smb, row0, col0, c);

    const float* bias_s = (const float*)(sm + OFF_BIAS);
#pragma unroll
    for (int mt = 0; mt < 4; mt++)
#pragma unroll
        for (int nt = 0; nt < 4; nt++) {
            int cl = wc * 32 + nt * 8 + (lane & 3) * 2;
            float bx = bias_s[cl], by = bias_s[cl + 1];
#pragma unroll
            for (int hh = 0; hh < 2; hh++) {
                int r = row0 + wr * 64 + mt * 16 + (lane >> 2) + hh * 8;
                float2 v = make_float2(c[mt][nt][2*hh] + bx, c[mt][nt][2*hh+1] + by);
                *(float2*)&Y[(size_t)r * DD + col0 + cl] = v;
            }
        }
}

// ---------------------------------------------------------------------------
// Flash attention on mma.sync (bf16 hi/lo, 3-term).
// CTA: 128 q rows x (b,h). 8 warps, warp w owns rows w*16..+15 over all 64 cols.
// ---------------------------------------------------------------------------
#define KST 72                     // bf16 elems per smem row
#define QBYTES (128*KST*2)         // 18432
#define KBYTES (64*KST*2)          // 9216
#define ATTN_SMEM (4*KBYTES)       // 36864 (Q stage uses same 2*QBYTES = 36864)

__global__ __launch_bounds__(256) void attn_mma_kernel()
{
    extern __shared__ char smc[];
    const uint32_t smb = smem_u32(smc);
    const int qt  = gridDim.x - 1 - blockIdx.x;     // heavy first
    const int bh  = blockIdx.y;
    const int tid = threadIdx.x;
    const int wid = tid >> 5, lane = tid & 31;
    const int lrow = lane & 15, lk = (lane >> 4) * 8;

    const size_t bhoff = (size_t)bh * SS * HD;
    const __nv_bfloat16* Qhg = g_qh + bhoff;
    const __nv_bfloat16* Qlg = g_ql + bhoff;
    const __nv_bfloat16* Khg = g_kh + bhoff;
    const __nv_bfloat16* Klg = g_kl + bhoff;
    const __nv_bfloat16* Vhg = g_vh + bhoff;
    const __nv_bfloat16* Vlg = g_vl + bhoff;

    // ---- Q stage: gmem -> smem -> register fragments ----
    {
        __nv_bfloat16* qs = (__nv_bfloat16*)smc;
#pragma unroll
        for (int i = 0; i < 4; i++) {
            int f = tid + i * 256;               // 0..1023
            int r = f >> 3, c8 = (f & 7) * 8;
            *(uint4*)&qs[r * KST + c8] =
                *(const uint4*)&Qhg[(size_t)(qt * 128 + r) * HD + c8];
            *(uint4*)&qs[128 * KST + r * KST + c8] =
                *(const uint4*)&Qlg[(size_t)(qt * 128 + r) * HD + c8];
        }
    }
    __syncthreads();

    uint32_t qh[4][4], ql[4][4];
#pragma unroll
    for (int t = 0; t < 4; t++) {
        uint32_t a = smb + (uint32_t)((wid * 16 + lrow) * KST + t * 16 + lk) * 2;
        ldsm4(qh[t], a);
        ldsm4(ql[t], a + QBYTES);
    }
    __syncthreads();   // Q smem consumed; buffer now free for K/V

    float o[8][4] = {};
    float m0 = -1e30f, m1 = -1e30f, l0 = 0.f, l1 = 0.f;

    const int ktmax = 2 * qt + 1;

    // register prefetch of tile 0
    uint4 pk[2][4];    // [i][{kh,kl,vh,vl}]
#pragma unroll
    for (int i = 0; i < 2; i++) {
        int f = tid + i * 256;
        int r = f >> 3, c8 = (f & 7) * 8;
        size_t go = (size_t)r * HD + c8;
        pk[i][0] = *(const uint4*)&Khg[go];
        pk[i][1] = *(const uint4*)&Klg[go];
        pk[i][2] = *(const uint4*)&Vhg[go];
        pk[i][3] = *(const uint4*)&Vlg[go];
    }

    for (int kt = 0; kt <= ktmax; kt++) {
        __syncthreads();   // previous tile fully consumed
        {
            __nv_bfloat16* ks = (__nv_bfloat16*)smc;
#pragma unroll
            for (int i = 0; i < 2; i++) {
                int f = tid + i * 256;
                int r = f >> 3, c8 = (f & 7) * 8;
                int so = r * KST + c8;
                *(uint4*)&ks[so]            = pk[i][0];
                *(uint4*)&ks[64*KST   + so] = pk[i][1];
                *(uint4*)&ks[2*64*KST + so] = pk[i][2];
                *(uint4*)&ks[3*64*KST + so] = pk[i][3];
            }
        }
        __syncthreads();

        if (kt < ktmax) {   // prefetch next tile during compute
#pragma unroll
            for (int i = 0; i < 2; i++) {
                int f = tid + i * 256;
                int r = f >> 3, c8 = (f & 7) * 8;
                size_t go = (size_t)((kt + 1) * 64 + r) * HD + c8;
                pk[i][0] = *(const uint4*)&Khg[go];
                pk[i][1] = *(const uint4*)&Klg[go];
                pk[i][2] = *(const uint4*)&Vhg[go];
                pk[i][3] = *(const uint4*)&Vlg[go];
            }
        }

        // ---- S = Q K^T ----
        float s[8][4] = {};
#pragma unroll
        for (int t = 0; t < 4; t++) {
#pragma unroll
            for (int g = 0; g < 4; g++) {
                uint32_t a = smb + (uint32_t)((g * 16 + lrow) * KST + t * 16 + lk) * 2;
                uint32_t rh[4], rl[4];
                ldsm4(rh, a);
                ldsm4(rl, a + KBYTES);
                uint32_t bh0[2] = {rh[0], rh[2]}, bh1[2] = {rh[1], rh[3]};
                uint32_t bl0[2] = {rl[0], rl[2]}, bl1[2] = {rl[1], rl[3]};
                mma16816(s[2*g],   qh[t], bh0);
                mma16816(s[2*g],   qh[t], bl0);
                mma16816(s[2*g],   ql[t], bh0);
                mma16816(s[2*g+1], qh[t], bh1);
                mma16816(s[2*g+1], qh[t], bl1);
                mma16816(s[2*g+1], ql[t], bh1);
            }
        }

        // ---- causal mask ----
        if (kt * 64 + 63 > qt * 128 + wid * 16) {
            int rbase = qt * 128 + wid * 16 + (lane >> 2);
            int cbase = kt * 64 + (lane & 3) * 2;
#pragma unroll
            for (int n = 0; n < 8; n++) {
                int cc = cbase + n * 8;
                if (cc     > rbase)     s[n][0] = -1e30f;
                if (cc + 1 > rbase)     s[n][1] = -1e30f;
                if (cc     > rbase + 8) s[n][2] = -1e30f;
                if (cc + 1 > rbase + 8) s[n][3] = -1e30f;
            }
        }

        // ---- online softmax (rows: lane>>2 and +8; 4 lanes share a row) ----
        float mx0 = -1e30f, mx1 = -1e30f;
#pragma unroll
        for (int n = 0; n < 8; n++) {
            mx0 = fmaxf(mx0, fmaxf(s[n][0], s[n][1]));
            mx1 = fmaxf(mx1, fmaxf(s[n][2], s[n][3]));
        }
        mx0 = fmaxf(mx0, __shfl_xor_sync(0xffffffffu, mx0, 1));
        mx0 = fmaxf(mx0, __shfl_xor_sync(0xffffffffu, mx0, 2));
        mx1 = fmaxf(mx1, __shfl_xor_sync(0xffffffffu, mx1, 1));
        mx1 = fmaxf(mx1, __shfl_xor_sync(0xffffffffu, mx1, 2));
        float mn0 = fmaxf(m0, mx0), mn1 = fmaxf(m1, mx1);
        float a0 = __expf(m0 - mn0), a1 = __expf(m1 - mn1);
        m0 = mn0; m1 = mn1;
        float lt0 = 0.f, lt1 = 0.f;
#pragma unroll
        for (int n = 0; n < 8; n++) {
            s[n][0] = __expf(s[n][0] - mn0); lt0 += s[n][0];
            s[n][1] = __expf(s[n][1] - mn0); lt0 += s[n][1];
            s[n][2] = __expf(s[n][2] - mn1); lt1 += s[n][2];
            s[n][3] = __expf(s[n][3] - mn1); lt1 += s[n][3];
        }
        lt0 += __shfl_xor_sync(0xffffffffu, lt0, 1);
        lt0 += __shfl_xor_sync(0xffffffffu, lt0, 2);
        lt1 += __shfl_xor_sync(0xffffffffu, lt1, 1);
        lt1 += __shfl_xor_sync(0xffffffffu, lt1, 2);
        l0 = l0 * a0 + lt0;
        l1 = l1 * a1 + lt1;
#pragma unroll
        for (int n = 0; n < 8; n++) {
            o[n][0] *= a0; o[n][1] *= a0; o[n][2] *= a1; o[n][3] *= a1;
        }

        // ---- O += P V : P frags from S registers, V via ldmatrix.trans ----
#pragma unroll
        for (int t = 0; t < 4; t++) {
            uint32_t ph[4], pl[4];
            split2(s[2*t][0],   s[2*t][1],   ph[0], pl[0]);
            split2(s[2*t][2],   s[2*t][3],   ph[1], pl[1]);
            split2(s[2*t+1][0], s[2*t+1][1], ph[2], pl[2]);
            split2(s[2*t+1][2], s[2*t+1][3], ph[3], pl[3]);
#pragma unroll
            for (int g = 0; g < 4; g++) {
                uint32_t a = smb + (uint32_t)(2*64*KST*2) +
                             (uint32_t)((t * 16 + lrow) * KST + g * 16 + lk) * 2;
                uint32_t rh[4], rl[4];
                ldsm4t(rh, a);
                ldsm4t(rl, a + KBYTES);
                uint32_t bh0[2] = {rh[0], rh[1]}, bh1[2] = {rh[2], rh[3]};
                uint32_t bl0[2] = {rl[0], rl[1]}, bl1[2] = {rl[2], rl[3]};
                mma16816(o[2*g],   ph, bh0);
                mma16816(o[2*g],   ph, bl0);
                mma16816(o[2*g],   pl, bh0);
                mma16816(o[2*g+1], ph, bh1);
                mma16816(o[2*g+1], ph, bl1);
                mma16816(o[2*g+1], pl, bh1);
            }
        }
    }

    // ---- epilogue: scale by 1/l, split, store hi/lo ----
    float inv0 = 1.f / l0, inv1 = 1.f / l1;
    const int b_ = bh / HH, h_ = bh % HH;
    const size_t r0 = (size_t)(b_ * SS + qt * 128 + wid * 16 + (lane >> 2));
#pragma unroll
    for (int n = 0; n < 8; n++) {
        int d = h_ * 64 + n * 8 + (lane & 3) * 2;
        uint32_t hp, lp;
        split2(o[n][0] * inv0, o[n][1] * inv0, hp, lp);
        *(uint32_t*)&g_oh[r0 * DD + d] = hp;
        *(uint32_t*)&g_ol[r0 * DD + d] = lp;
        split2(o[n][2] * inv1, o[n][3] * inv1, hp, lp);
        *(uint32_t*)&g_oh[(r0 + 8) * DD + d] = hp;
        *(uint32_t*)&g_ol[(r0 + 8) * DD + d] = lp;
    }
}

// ---------------------------------------------------------------------------
extern "C" void kernel_launch(void* const* d_in, const int* in_sizes, int n_in,
                              void* d_out, int out_size)
{
    const float* x    = (const float*)d_in[0];
    const float* Wqkv = (const float*)d_in[1];
    const float* bqkv = (const float*)d_in[2];
    const float* Wout = (const float*)d_in[3];
    const float* bout = (const float*)d_in[4];
    float* out = (float*)d_out;

    cudaFuncSetAttribute(attn_mma_kernel, cudaFuncAttributeMaxDynamicSharedMemorySize, ATTN_SMEM);

    __nv_bfloat16 *xh, *xl, *w1h, *w1l, *w2h, *w2l;
    cudaGetSymbolAddress((void**)&xh,  g_xh);  cudaGetSymbolAddress((void**)&xl,  g_xl);
    cudaGetSymbolAddress((void**)&w1h, g_w1h); cudaGetSymbolAddress((void**)&w1l, g_w1l);
    cudaGetSymbolAddress((void**)&w2h, g_w2h); cudaGetSymbolAddress((void**)&w2l, g_w2l);

    split_kernel<<<MM * DD / 1024, 256>>>(x, xh, xl);
    transpose_split_kernel<<<dim3(N3 / 32, DD / 32), dim3(32, 8)>>>(Wqkv, w1h, w1l, DD, N3);
    transpose_split_kernel<<<dim3(DD / 32, DD / 32), dim3(32, 8)>>>(Wout, w2h, w2l, DD, DD);

    gemm_qkv_tc<<<dim3(N3 / 128, MM / 128), 256, GEMM_SMEM>>>(bqkv);
    attn_mma_kernel<<<dim3(SS / 128, BB * HH), 256, ATTN_SMEM>>>();
    gemm_out_tc<<<dim3(DD / 128, MM / 128), 256, GEMM_SMEM>>>(bout, out);
}

// round 7
// speedup vs baseline: 6.1149x; 1.0059x over previous
#include <cuda_runtime.h>
#include <cuda_bf16.h>
#include <cstdint>

#define BB 2
#define SS 4096
#define DD 768
#define HH 12
#define HD 64
#define N3 (3*DD)
#define MM (BB*SS)

// bf16 hi/lo scratch
__device__ __align__(16) __nv_bfloat16 g_qh[BB*HH*SS*HD], g_ql[BB*HH*SS*HD];
__device__ __align__(16) __nv_bfloat16 g_kh[BB*HH*SS*HD], g_kl[BB*HH*SS*HD];
__device__ __align__(16) __nv_bfloat16 g_vh[BB*HH*SS*HD], g_vl[BB*HH*SS*HD];
__device__ __align__(16) __nv_bfloat16 g_oh[MM*DD],  g_ol[MM*DD];
__device__ __align__(16) __nv_bfloat16 g_xh[MM*DD],  g_xl[MM*DD];
__device__ __align__(16) __nv_bfloat16 g_w1h[N3*DD], g_w1l[N3*DD];
__device__ __align__(16) __nv_bfloat16 g_w2h[DD*DD], g_w2l[DD*DD];

// ---------------- helpers ----------------
__device__ __forceinline__ uint32_t smem_u32(const void* p) {
    uint32_t a;
    asm("{ .reg .u64 t; cvta.to.shared.u64 t, %1; cvt.u32.u64 %0, t; }" : "=r"(a) : "l"(p));
    return a;
}
__device__ __forceinline__ void ldsm4(uint32_t* r, uint32_t addr) {
    asm volatile("ldmatrix.sync.aligned.m8n8.x4.shared.b16 {%0,%1,%2,%3}, [%4];"
        : "=r"(r[0]), "=r"(r[1]), "=r"(r[2]), "=r"(r[3]) : "r"(addr));
}
__device__ __forceinline__ void ldsm4t(uint32_t* r, uint32_t addr) {
    asm volatile("ldmatrix.sync.aligned.m8n8.x4.trans.shared.b16 {%0,%1,%2,%3}, [%4];"
        : "=r"(r[0]), "=r"(r[1]), "=r"(r[2]), "=r"(r[3]) : "r"(addr));
}
__device__ __forceinline__ void mma16816(float* c, const uint32_t* a, const uint32_t* b) {
    asm volatile(
        "mma.sync.aligned.m16n8k16.row.col.f32.bf16.bf16.f32 "
        "{%0,%1,%2,%3}, {%4,%5,%6,%7}, {%8,%9}, {%0,%1,%2,%3};"
        : "+f"(c[0]), "+f"(c[1]), "+f"(c[2]), "+f"(c[3])
        : "r"(a[0]), "r"(a[1]), "r"(a[2]), "r"(a[3]), "r"(b[0]), "r"(b[1]));
}
__device__ __forceinline__ uint32_t packbf(float x, float y) {
    __nv_bfloat162 h = __floats2bfloat162_rn(x, y);
    return *(uint32_t*)&h;
}
__device__ __forceinline__ void split2(float x, float y, uint32_t& h, uint32_t& l) {
    __nv_bfloat16 hx = __float2bfloat16(x), hy = __float2bfloat16(y);
    h = packbf(x, y);
    l = packbf(x - __bfloat162float(hx), y - __bfloat162float(hy));
}

// ---------------- GEMM smem layout (2 stages) ----------------
#define TROW 80
#define OFF_AH 0
#define OFF_AL (OFF_AH + 128*TROW)
#define OFF_BH (OFF_AL + 128*TROW)
#define OFF_BL (OFF_BH + 128*TROW)
#define STAGE_B (4*128*TROW)                  // 40960 per stage
#define OFF_BIAS (2*STAGE_B)                  // 81920
#define GEMM_SMEM (OFF_BIAS + 512)            // 82432
#define NCHUNK (DD/32)                        // 24

// ---------------------------------------------------------------------------
__global__ __launch_bounds__(256) void split_kernel(
    const float* __restrict__ src, __nv_bfloat16* __restrict__ hi,
    __nv_bfloat16* __restrict__ lo)
{
    int i = (blockIdx.x * 256 + threadIdx.x) * 4;
    float4 v = *(const float4*)(src + i);
    uint32_t h0, l0, h1, l1;
    split2(v.x, v.y, h0, l0);
    split2(v.z, v.w, h1, l1);
    *(uint32_t*)(hi + i) = h0; *(uint32_t*)(hi + i + 2) = h1;
    *(uint32_t*)(lo + i) = l0; *(uint32_t*)(lo + i + 2) = l1;
}

__global__ void transpose_split_kernel(
    const float* __restrict__ src, __nv_bfloat16* __restrict__ hi,
    __nv_bfloat16* __restrict__ lo, int R, int C)
{
    __shared__ float t[32][33];
    int bx = blockIdx.x * 32, by = blockIdx.y * 32;
    int tx = threadIdx.x, ty = threadIdx.y;
#pragma unroll
    for (int i = 0; i < 32; i += 8)
        t[ty + i][tx] = src[(size_t)(by + ty + i) * C + bx + tx];
    __syncthreads();
#pragma unroll
    for (int i = 0; i < 32; i += 8) {
        float v = t[tx][ty + i];
        __nv_bfloat16 h = __float2bfloat16(v);
        size_t o = (size_t)(bx + ty + i) * R + by + tx;
        hi[o] = h; lo[o] = __float2bfloat16(v - __bfloat162float(h));
    }
}

// ---------------------------------------------------------------------------
// bf16x3 MMA mainloop, 2-stage pipelined: one __syncthreads per chunk.
// ---------------------------------------------------------------------------
__device__ __forceinline__ void gemm_mainloop(
    const __nv_bfloat16* __restrict__ Ah, const __nv_bfloat16* __restrict__ Al,
    const __nv_bfloat16* __restrict__ Bh, const __nv_bfloat16* __restrict__ Bl,
    const float* __restrict__ bias_g,
    char* sm, uint32_t smb, int row0, int col0, float c[4][4][4])
{
    const int tid  = threadIdx.x;
    const int wid  = tid >> 5, lane = tid & 31;
    const int wr   = wid >> 2, wc = wid & 3;
    const int arow = tid >> 1;
    const int ak   = (tid & 1) * 16;

    if (tid < 128) ((float*)(sm + OFF_BIAS))[tid] = bias_g[col0 + tid];

    const size_t aoff = (size_t)(row0 + arow) * DD + ak;
    const size_t boff = (size_t)(col0 + arow) * DD + ak;
    const uint32_t sts = (uint32_t)(arow * TROW + ak * 2);

    uint4 pa[4], pb[4];
    pa[0] = *(const uint4*)(Ah + aoff); pa[1] = *(const uint4*)(Ah + aoff + 8);
    pa[2] = *(const uint4*)(Al + aoff); pa[3] = *(const uint4*)(Al + aoff + 8);
    pb[0] = *(const uint4*)(Bh + boff); pb[1] = *(const uint4*)(Bh + boff + 8);
    pb[2] = *(const uint4*)(Bl + boff); pb[3] = *(const uint4*)(Bl + boff + 8);

    const int lrow = lane & 15;
    const int lk   = (lane >> 4) * 8;

    for (int ch = 0; ch < NCHUNK; ch++) {
        const uint32_t stg = (uint32_t)(ch & 1) * STAGE_B;
        *(uint4*)(sm + stg + OFF_AH + sts)      = pa[0];
        *(uint4*)(sm + stg + OFF_AH + sts + 16) = pa[1];
        *(uint4*)(sm + stg + OFF_AL + sts)      = pa[2];
        *(uint4*)(sm + stg + OFF_AL + sts + 16) = pa[3];
        *(uint4*)(sm + stg + OFF_BH + sts)      = pb[0];
        *(uint4*)(sm + stg + OFF_BH + sts + 16) = pb[1];
        *(uint4*)(sm + stg + OFF_BL + sts)      = pb[2];
        *(uint4*)(sm + stg + OFF_BL + sts + 16) = pb[3];
        __syncthreads();

        if (ch + 1 < NCHUNK) {
            const int k1 = (ch + 1) * 32;
            pa[0] = *(const uint4*)(Ah + aoff + k1); pa[1] = *(const uint4*)(Ah + aoff + k1 + 8);
            pa[2] = *(const uint4*)(Al + aoff + k1); pa[3] = *(const uint4*)(Al + aoff + k1 + 8);
            pb[0] = *(const uint4*)(Bh + boff + k1); pb[1] = *(const uint4*)(Bh + boff + k1 + 8);
            pb[2] = *(const uint4*)(Bl + boff + k1); pb[3] = *(const uint4*)(Bl + boff + k1 + 8);
        }

#pragma unroll
        for (int ks = 0; ks < 2; ks++) {
            const uint32_t kb = (uint32_t)((ks * 16 + lk) * 2);
            uint32_t a_hi[4][4], a_lo[4][4], b_hi[4][2], b_lo[4][2];
#pragma unroll
            for (int mt = 0; mt < 4; mt++) {
                uint32_t ra = smb + stg + (uint32_t)((wr * 64 + mt * 16 + lrow) * TROW) + kb;
                ldsm4(a_hi[mt], OFF_AH + ra);
                ldsm4(a_lo[mt], OFF_AL + ra);
            }
#pragma unroll
            for (int g = 0; g < 2; g++) {
                uint32_t rb = smb + stg + (uint32_t)((wc * 32 + g * 16 + lrow) * TROW) + kb;
                uint32_t r[4];
                ldsm4(r, OFF_BH + rb);
                b_hi[2*g][0] = r[0]; b_hi[2*g][1] = r[2];
                b_hi[2*g+1][0] = r[1]; b_hi[2*g+1][1] = r[3];
                ldsm4(r, OFF_BL + rb);
                b_lo[2*g][0] = r[0]; b_lo[2*g][1] = r[2];
                b_lo[2*g+1][0] = r[1]; b_lo[2*g+1][1] = r[3];
            }
#pragma unroll
            for (int mt = 0; mt < 4; mt++)
#pragma unroll
                for (int nt = 0; nt < 4; nt++) {
                    mma16816(c[mt][nt], a_hi[mt], b_hi[nt]);
                    mma16816(c[mt][nt], a_hi[mt], b_lo[nt]);
                    mma16816(c[mt][nt], a_lo[mt], b_hi[nt]);
                }
        }
    }
    __syncthreads();
}

// ---------------------------------------------------------------------------
// GEMM1: qkv projection -> bf16 hi/lo Q(scaled)/K/V in [b,h,s,d]
// ---------------------------------------------------------------------------
__global__ __launch_bounds__(256) void gemm_qkv_tc(const float* __restrict__ bqkv)
{
    extern __shared__ char sm[];
    const uint32_t smb = smem_u32(sm);
    const int col0 = blockIdx.x * 128;
    const int row0 = blockIdx.y * 128;
    const int tid = threadIdx.x, wid = tid >> 5, lane = tid & 31;
    const int wr = wid >> 2, wc = wid & 3;

    float c[4][4][4] = {};
    gemm_mainloop(g_xh, g_xl, g_w1h, g_w1l, bqkv, sm, smb, row0, col0, c);

    const float* bias_s = (const float*)(sm + OFF_BIAS);
    const int which = col0 / DD;
    const int h = (col0 % DD) / HD + (wc >> 1);
    const int b_ = row0 >> 12;
    const int s0 = row0 & 4095;
    const float scale = (which == 0) ? 0.125f : 1.0f;

    __nv_bfloat16* dh = (which == 0) ? g_qh : (which == 1) ? g_kh : g_vh;
    __nv_bfloat16* dl = (which == 0) ? g_ql : (which == 1) ? g_kl : g_vl;
    const size_t base = (size_t)(b_ * HH + h) * SS * HD;

#pragma unroll
    for (int mt = 0; mt < 4; mt++)
#pragma unroll
        for (int nt = 0; nt < 4; nt++) {
            int d = (wc & 1) * 32 + nt * 8 + (lane & 3) * 2;
            float bx = bias_s[(wc >> 1) * 64 + d];
            float by = bias_s[(wc >> 1) * 64 + d + 1];
#pragma unroll
            for (int hh = 0; hh < 2; hh++) {
                int gs = s0 + wr * 64 + mt * 16 + (lane >> 2) + hh * 8;
                float v0 = (c[mt][nt][2*hh]   + bx) * scale;
                float v1 = (c[mt][nt][2*hh+1] + by) * scale;
                uint32_t hp, lp;
                split2(v0, v1, hp, lp);
                *(uint32_t*)&dh[base + (size_t)gs * HD + d] = hp;
                *(uint32_t*)&dl[base + (size_t)gs * HD + d] = lp;
            }
        }
}

// ---------------------------------------------------------------------------
// GEMM2: out projection
// ---------------------------------------------------------------------------
__global__ __launch_bounds__(256) void gemm_out_tc(const float* __restrict__ bout,
                                                   float* __restrict__ Y)
{
    extern __shared__ char sm[];
    const uint32_t smb = smem_u32(sm);
    const int col0 = blockIdx.x * 128;
    const int row0 = blockIdx.y * 128;
    const int tid = threadIdx.x, wid = tid >> 5, lane = tid & 31;
    const int wr = wid >> 2, wc = wid & 3;

    float c[4][4][4] = {};
    gemm_mainloop(g_oh, g_ol, g_w2h, g_w2l, bout, sm, smb, row0, col0, c);

    const float* bias_s = (const float*)(sm + OFF_BIAS);
#pragma unroll
    for (int mt = 0; mt < 4; mt++)
#pragma unroll
        for (int nt = 0; nt < 4; nt++) {
            int cl = wc * 32 + nt * 8 + (lane & 3) * 2;
            float bx = bias_s[cl], by = bias_s[cl + 1];
#pragma unroll
            for (int hh = 0; hh < 2; hh++) {
                int r = row0 + wr * 64 + mt * 16 + (lane >> 2) + hh * 8;
                float2 v = make_float2(c[mt][nt][2*hh] + bx, c[mt][nt][2*hh+1] + by);
                *(float2*)&Y[(size_t)r * DD + col0 + cl] = v;
            }
        }
}

// ---------------------------------------------------------------------------
// Flash attention on mma.sync (bf16 hi/lo, 3-term), 2-stage pipelined K/V.
// ---------------------------------------------------------------------------
#define KST 72
#define QBYTES (128*KST*2)          // 18432
#define KBYTES (64*KST*2)           // 9216
#define ASTAGE (4*KBYTES)           // 36864 per stage
#define ATTN_SMEM (2*ASTAGE)        // 73728

__global__ __launch_bounds__(256) void attn_mma_kernel()
{
    extern __shared__ char smc[];
    const uint32_t smb = smem_u32(smc);
    const int qt  = gridDim.x - 1 - blockIdx.x;     // heavy first
    const int bh  = blockIdx.y;
    const int tid = threadIdx.x;
    const int wid = tid >> 5, lane = tid & 31;
    const int lrow = lane & 15, lk = (lane >> 4) * 8;

    const size_t bhoff = (size_t)bh * SS * HD;
    const __nv_bfloat16* Qhg = g_qh + bhoff;
    const __nv_bfloat16* Qlg = g_ql + bhoff;
    const __nv_bfloat16* Khg = g_kh + bhoff;
    const __nv_bfloat16* Klg = g_kl + bhoff;
    const __nv_bfloat16* Vhg = g_vh + bhoff;
    const __nv_bfloat16* Vlg = g_vl + bhoff;

    // ---- Q stage: gmem -> smem -> register fragments ----
    {
        __nv_bfloat16* qs = (__nv_bfloat16*)smc;
#pragma unroll
        for (int i = 0; i < 4; i++) {
            int f = tid + i * 256;
            int r = f >> 3, c8 = (f & 7) * 8;
            *(uint4*)&qs[r * KST + c8] =
                *(const uint4*)&Qhg[(size_t)(qt * 128 + r) * HD + c8];
            *(uint4*)&qs[128 * KST + r * KST + c8] =
                *(const uint4*)&Qlg[(size_t)(qt * 128 + r) * HD + c8];
        }
    }
    __syncthreads();

    uint32_t qh[4][4], ql[4][4];
#pragma unroll
    for (int t = 0; t < 4; t++) {
        uint32_t a = smb + (uint32_t)((wid * 16 + lrow) * KST + t * 16 + lk) * 2;
        ldsm4(qh[t], a);
        ldsm4(ql[t], a + QBYTES);
    }
    __syncthreads();   // Q smem consumed; stage 0 free for K/V

    float o[8][4] = {};
    float m0 = -1e30f, m1 = -1e30f, l0 = 0.f, l1 = 0.f;

    const int ktmax = 2 * qt + 1;

    uint4 pk[2][4];
#pragma unroll
    for (int i = 0; i < 2; i++) {
        int f = tid + i * 256;
        int r = f >> 3, c8 = (f & 7) * 8;
        size_t go = (size_t)r * HD + c8;
        pk[i][0] = *(const uint4*)&Khg[go];
        pk[i][1] = *(const uint4*)&Klg[go];
        pk[i][2] = *(const uint4*)&Vhg[go];
        pk[i][3] = *(const uint4*)&Vlg[go];
    }

    for (int kt = 0; kt <= ktmax; kt++) {
        const uint32_t stg = (uint32_t)(kt & 1) * ASTAGE;
        {
            __nv_bfloat16* ks = (__nv_bfloat16*)(smc + stg);
#pragma unroll
            for (int i = 0; i < 2; i++) {
                int f = tid + i * 256;
                int r = f >> 3, c8 = (f & 7) * 8;
                int so = r * KST + c8;
                *(uint4*)&ks[so]            = pk[i][0];
                *(uint4*)&ks[64*KST   + so] = pk[i][1];
                *(uint4*)&ks[2*64*KST + so] = pk[i][2];
                *(uint4*)&ks[3*64*KST + so] = pk[i][3];
            }
        }
        __syncthreads();

        if (kt < ktmax) {
#pragma unroll
            for (int i = 0; i < 2; i++) {
                int f = tid + i * 256;
                int r = f >> 3, c8 = (f & 7) * 8;
                size_t go = (size_t)((kt + 1) * 64 + r) * HD + c8;
                pk[i][0] = *(const uint4*)&Khg[go];
                pk[i][1] = *(const uint4*)&Klg[go];
                pk[i][2] = *(const uint4*)&Vhg[go];
                pk[i][3] = *(const uint4*)&Vlg[go];
            }
        }

        // ---- S = Q K^T ----
        float s[8][4] = {};
#pragma unroll
        for (int t = 0; t < 4; t++) {
#pragma unroll
            for (int g = 0; g < 4; g++) {
                uint32_t a = smb + stg + (uint32_t)((g * 16 + lrow) * KST + t * 16 + lk) * 2;
                uint32_t rh[4], rl[4];
                ldsm4(rh, a);
                ldsm4(rl, a + KBYTES);
                uint32_t bh0[2] = {rh[0], rh[2]}, bh1[2] = {rh[1], rh[3]};
                uint32_t bl0[2] = {rl[0], rl[2]}, bl1[2] = {rl[1], rl[3]};
                mma16816(s[2*g],   qh[t], bh0);
                mma16816(s[2*g],   qh[t], bl0);
                mma16816(s[2*g],   ql[t], bh0);
                mma16816(s[2*g+1], qh[t], bh1);
                mma16816(s[2*g+1], qh[t], bl1);
                mma16816(s[2*g+1], ql[t], bh1);
            }
        }

        // ---- causal mask ----
        if (kt * 64 + 63 > qt * 128 + wid * 16) {
            int rbase = qt * 128 + wid * 16 + (lane >> 2);
            int cbase = kt * 64 + (lane & 3) * 2;
#pragma unroll
            for (int n = 0; n < 8; n++) {
                int cc = cbase + n * 8;
                if (cc     > rbase)     s[n][0] = -1e30f;
                if (cc + 1 > rbase)     s[n][1] = -1e30f;
                if (cc     > rbase + 8) s[n][2] = -1e30f;
                if (cc + 1 > rbase + 8) s[n][3] = -1e30f;
            }
        }

        // ---- online softmax ----
        float mx0 = -1e30f, mx1 = -1e30f;
#pragma unroll
        for (int n = 0; n < 8; n++) {
            mx0 = fmaxf(mx0, fmaxf(s[n][0], s[n][1]));
            mx1 = fmaxf(mx1, fmaxf(s[n][2], s[n][3]));
        }
        mx0 = fmaxf(mx0, __shfl_xor_sync(0xffffffffu, mx0, 1));
        mx0 = fmaxf(mx0, __shfl_xor_sync(0xffffffffu, mx0, 2));
        mx1 = fmaxf(mx1, __shfl_xor_sync(0xffffffffu, mx1, 1));
        mx1 = fmaxf(mx1, __shfl_xor_sync(0xffffffffu, mx1, 2));
        float mn0 = fmaxf(m0, mx0), mn1 = fmaxf(m1, mx1);
        float a0 = __expf(m0 - mn0), a1 = __expf(m1 - mn1);
        m0 = mn0; m1 = mn1;
        float lt0 = 0.f, lt1 = 0.f;
#pragma unroll
        for (int n = 0; n < 8; n++) {
            s[n][0] = __expf(s[n][0] - mn0); lt0 += s[n][0];
            s[n][1] = __expf(s[n][1] - mn0); lt0 += s[n][1];
            s[n][2] = __expf(s[n][2] - mn1); lt1 += s[n][2];
            s[n][3] = __expf(s[n][3] - mn1); lt1 += s[n][3];
        }
        lt0 += __shfl_xor_sync(0xffffffffu, lt0, 1);
        lt0 += __shfl_xor_sync(0xffffffffu, lt0, 2);
        lt1 += __shfl_xor_sync(0xffffffffu, lt1, 1);
        lt1 += __shfl_xor_sync(0xffffffffu, lt1, 2);
        l0 = l0 * a0 + lt0;
        l1 = l1 * a1 + lt1;
#pragma unroll
        for (int n = 0; n < 8; n++) {
            o[n][0] *= a0; o[n][1] *= a0; o[n][2] *= a1; o[n][3] *= a1;
        }

        // ---- O += P V ----
#pragma unroll
        for (int t = 0; t < 4; t++) {
            uint32_t ph[4], pl[4];
            split2(s[2*t][0],   s[2*t][1],   ph[0], pl[0]);
            split2(s[2*t][2],   s[2*t][3],   ph[1], pl[1]);
            split2(s[2*t+1][0], s[2*t+1][1], ph[2], pl[2]);
            split2(s[2*t+1][2], s[2*t+1][3], ph[3], pl[3]);
#pragma unroll
            for (int g = 0; g < 4; g++) {
                uint32_t a = smb + stg + (uint32_t)(2*64*KST*2) +
                             (uint32_t)((t * 16 + lrow) * KST + g * 16 + lk) * 2;
                uint32_t rh[4], rl[4];
                ldsm4t(rh, a);
                ldsm4t(rl, a + KBYTES);
                uint32_t bh0[2] = {rh[0], rh[1]}, bh1[2] = {rh[2], rh[3]};
                uint32_t bl0[2] = {rl[0], rl[1]}, bl1[2] = {rl[2], rl[3]};
                mma16816(o[2*g],   ph, bh0);
                mma16816(o[2*g],   ph, bl0);
                mma16816(o[2*g],   pl, bh0);
                mma16816(o[2*g+1], ph, bh1);
                mma16816(o[2*g+1], ph, bl1);
                mma16816(o[2*g+1], pl, bh1);
            }
        }
    }

    // ---- epilogue ----
    float inv0 = 1.f / l0, inv1 = 1.f / l1;
    const int b_ = bh / HH, h_ = bh % HH;
    const size_t r0 = (size_t)(b_ * SS + qt * 128 + wid * 16 + (lane >> 2));
#pragma unroll
    for (int n = 0; n < 8; n++) {
        int d = h_ * 64 + n * 8 + (lane & 3) * 2;
        uint32_t hp, lp;
        split2(o[n][0] * inv0, o[n][1] * inv0, hp, lp);
        *(uint32_t*)&g_oh[r0 * DD + d] = hp;
        *(uint32_t*)&g_ol[r0 * DD + d] = lp;
        split2(o[n][2] * inv1, o[n][3] * inv1, hp, lp);
        *(uint32_t*)&g_oh[(r0 + 8) * DD + d] = hp;
        *(uint32_t*)&g_ol[(r0 + 8) * DD + d] = lp;
    }
}

// ---------------------------------------------------------------------------
extern "C" void kernel_launch(void* const* d_in, const int* in_sizes, int n_in,
                              void* d_out, int out_size)
{
    const float* x    = (const float*)d_in[0];
    const float* Wqkv = (const float*)d_in[1];
    const float* bqkv = (const float*)d_in[2];
    const float* Wout = (const float*)d_in[3];
    const float* bout = (const float*)d_in[4];
    float* out = (float*)d_out;

    cudaFuncSetAttribute(attn_mma_kernel, cudaFuncAttributeMaxDynamicSharedMemorySize, ATTN_SMEM);
    cudaFuncSetAttribute(gemm_qkv_tc, cudaFuncAttributeMaxDynamicSharedMemorySize, GEMM_SMEM);
    cudaFuncSetAttribute(gemm_out_tc, cudaFuncAttributeMaxDynamicSharedMemorySize, GEMM_SMEM);

    __nv_bfloat16 *xh, *xl, *w1h, *w1l, *w2h, *w2l;
    cudaGetSymbolAddress((void**)&xh,  g_xh);  cudaGetSymbolAddress((void**)&xl,  g_xl);
    cudaGetSymbolAddress((void**)&w1h, g_w1h); cudaGetSymbolAddress((void**)&w1l, g_w1l);
    cudaGetSymbolAddress((void**)&w2h, g_w2h); cudaGetSymbolAddress((void**)&w2l, g_w2l);

    split_kernel<<<MM * DD / 1024, 256>>>(x, xh, xl);
    transpose_split_kernel<<<dim3(N3 / 32, DD / 32), dim3(32, 8)>>>(Wqkv, w1h, w1l, DD, N3);
    transpose_split_kernel<<<dim3(DD / 32, DD / 32), dim3(32, 8)>>>(Wout, w2h, w2l, DD, DD);

    gemm_qkv_tc<<<dim3(N3 / 128, MM / 128), 256, GEMM_SMEM>>>(bqkv);
    attn_mma_kernel<<<dim3(SS / 128, BB * HH), 256, ATTN_SMEM>>>();
    gemm_out_tc<<<dim3(DD / 128, MM / 128), 256, GEMM_SMEM>>>(bout, out);
}

// round 8
// speedup vs baseline: 6.3186x; 1.0333x over previous
#include <cuda_runtime.h>
#include <cuda_bf16.h>
#include <cstdint>

#define BB 2
#define SS 4096
#define DD 768
#define HH 12
#define HD 64
#define N3 (3*DD)
#define MM (BB*SS)

// bf16 hi/lo scratch
__device__ __align__(16) __nv_bfloat16 g_qh[BB*HH*SS*HD], g_ql[BB*HH*SS*HD];
__device__ __align__(16) __nv_bfloat16 g_kh[BB*HH*SS*HD], g_kl[BB*HH*SS*HD];
__device__ __align__(16) __nv_bfloat16 g_vh[BB*HH*SS*HD], g_vl[BB*HH*SS*HD];
__device__ __align__(16) __nv_bfloat16 g_oh[MM*DD],  g_ol[MM*DD];
__device__ __align__(16) __nv_bfloat16 g_xh[MM*DD],  g_xl[MM*DD];
__device__ __align__(16) __nv_bfloat16 g_w1h[N3*DD], g_w1l[N3*DD];
__device__ __align__(16) __nv_bfloat16 g_w2h[DD*DD], g_w2l[DD*DD];

// ---------------- helpers ----------------
__device__ __forceinline__ uint32_t smem_u32(const void* p) {
    uint32_t a;
    asm("{ .reg .u64 t; cvta.to.shared.u64 t, %1; cvt.u32.u64 %0, t; }" : "=r"(a) : "l"(p));
    return a;
}
__device__ __forceinline__ void ldsm4(uint32_t* r, uint32_t addr) {
    asm volatile("ldmatrix.sync.aligned.m8n8.x4.shared.b16 {%0,%1,%2,%3}, [%4];"
        : "=r"(r[0]), "=r"(r[1]), "=r"(r[2]), "=r"(r[3]) : "r"(addr));
}
__device__ __forceinline__ void ldsm4t(uint32_t* r, uint32_t addr) {
    asm volatile("ldmatrix.sync.aligned.m8n8.x4.trans.shared.b16 {%0,%1,%2,%3}, [%4];"
        : "=r"(r[0]), "=r"(r[1]), "=r"(r[2]), "=r"(r[3]) : "r"(addr));
}
__device__ __forceinline__ void mma16816(float* c, const uint32_t* a, const uint32_t* b) {
    asm volatile(
        "mma.sync.aligned.m16n8k16.row.col.f32.bf16.bf16.f32 "
        "{%0,%1,%2,%3}, {%4,%5,%6,%7}, {%8,%9}, {%0,%1,%2,%3};"
        : "+f"(c[0]), "+f"(c[1]), "+f"(c[2]), "+f"(c[3])
        : "r"(a[0]), "r"(a[1]), "r"(a[2]), "r"(a[3]), "r"(b[0]), "r"(b[1]));
}
__device__ __forceinline__ uint32_t packbf(float x, float y) {
    __nv_bfloat162 h = __floats2bfloat162_rn(x, y);
    return *(uint32_t*)&h;
}
__device__ __forceinline__ void split2(float x, float y, uint32_t& h, uint32_t& l) {
    __nv_bfloat16 hx = __float2bfloat16(x), hy = __float2bfloat16(y);
    h = packbf(x, y);
    l = packbf(x - __bfloat162float(hx), y - __bfloat162float(hy));
}
#define CP_ASYNC16(dst, src) \
    asm volatile("cp.async.ca.shared.global [%0], [%1], 16;" :: "r"(dst), "l"(src))
#define CP_COMMIT() asm volatile("cp.async.commit_group;")
#define CP_WAIT(n)  asm volatile("cp.async.wait_group %0;" :: "n"(n))

// ---------------- GEMM smem layout: 3 cp.async stages ----------------
#define TROW 80
#define BUF_B (128*TROW)            // 10240 per operand buffer
#define STAGE_B (4*BUF_B)           // 40960 per stage (AH,AL,BH,BL)
#define NSTG 3
#define OFF_BIAS (NSTG*STAGE_B)     // 122880
#define GEMM_SMEM (OFF_BIAS + 512)  // 123392
#define NCHUNK (DD/32)              // 24

// ---------------------------------------------------------------------------
__global__ __launch_bounds__(256) void split_kernel(
    const float* __restrict__ src, __nv_bfloat16* __restrict__ hi,
    __nv_bfloat16* __restrict__ lo)
{
    int i = (blockIdx.x * 256 + threadIdx.x) * 4;
    float4 v = *(const float4*)(src + i);
    uint32_t h0, l0, h1, l1;
    split2(v.x, v.y, h0, l0);
    split2(v.z, v.w, h1, l1);
    *(uint32_t*)(hi + i) = h0; *(uint32_t*)(hi + i + 2) = h1;
    *(uint32_t*)(lo + i) = l0; *(uint32_t*)(lo + i + 2) = l1;
}

__global__ void transpose_split_kernel(
    const float* __restrict__ src, __nv_bfloat16* __restrict__ hi,
    __nv_bfloat16* __restrict__ lo, int R, int C)
{
    __shared__ float t[32][33];
    int bx = blockIdx.x * 32, by = blockIdx.y * 32;
    int tx = threadIdx.x, ty = threadIdx.y;
#pragma unroll
    for (int i = 0; i < 32; i += 8)
        t[ty + i][tx] = src[(size_t)(by + ty + i) * C + bx + tx];
    __syncthreads();
#pragma unroll
    for (int i = 0; i < 32; i += 8) {
        float v = t[tx][ty + i];
        __nv_bfloat16 h = __float2bfloat16(v);
        size_t o = (size_t)(bx + ty + i) * R + by + tx;
        hi[o] = h; lo[o] = __float2bfloat16(v - __bfloat162float(h));
    }
}

// ---------------------------------------------------------------------------
// bf16x3 MMA mainloop: 512 threads, 16 warps (4x4), 32x32 warp tiles,
// 3-stage cp.async pipeline. Result c[2][4][4] per thread.
// ---------------------------------------------------------------------------
__device__ __forceinline__ void gemm_mainloop(
    const __nv_bfloat16* __restrict__ Ah, const __nv_bfloat16* __restrict__ Al,
    const __nv_bfloat16* __restrict__ Bh, const __nv_bfloat16* __restrict__ Bl,
    const float* __restrict__ bias_g,
    char* sm, uint32_t smb, int row0, int col0, float c[2][4][4])
{
    const int tid  = threadIdx.x;
    const int wid  = tid >> 5, lane = tid & 31;
    const int wr   = wid >> 2, wc = wid & 3;

    if (tid < 128) ((float*)(sm + OFF_BIAS))[tid] = bias_g[col0 + tid];

    // cp.async mapping: thread -> (row = tid>>2, k-quarter = (tid&3)*8)
    const int crow = tid >> 2;
    const int ck8  = (tid & 3) * 8;
    const __nv_bfloat16* gA_h = Ah + (size_t)(row0 + crow) * DD + ck8;
    const __nv_bfloat16* gA_l = Al + (size_t)(row0 + crow) * DD + ck8;
    const __nv_bfloat16* gB_h = Bh + (size_t)(col0 + crow) * DD + ck8;
    const __nv_bfloat16* gB_l = Bl + (size_t)(col0 + crow) * DD + ck8;
    const uint32_t sdst = smb + (uint32_t)(crow * TROW + ck8 * 2);

    // prologue: chunks 0 and 1
#pragma unroll
    for (int p = 0; p < 2; p++) {
        const uint32_t so = sdst + (uint32_t)p * STAGE_B;
        const int ko = p * 32;
        CP_ASYNC16(so,             gA_h + ko);
        CP_ASYNC16(so + BUF_B,     gA_l + ko);
        CP_ASYNC16(so + 2*BUF_B,   gB_h + ko);
        CP_ASYNC16(so + 3*BUF_B,   gB_l + ko);
        CP_COMMIT();
    }

    const int lrow = lane & 15;
    const int lk   = (lane >> 4) * 8;

    int st = 0;
    for (int ch = 0; ch < NCHUNK; ch++) {
        CP_WAIT(1);          // group for chunk ch complete
        __syncthreads();     // all threads' copies visible; prev compute done

        // issue chunk ch+2 into stage (ch+2)%3
        {
            int nx = ch + 2;
            if (nx < NCHUNK) {
                int stn = st + 2; if (stn >= NSTG) stn -= NSTG;
                const uint32_t so = sdst + (uint32_t)stn * STAGE_B;
                const int ko = nx * 32;
                CP_ASYNC16(so,           gA_h + ko);
                CP_ASYNC16(so + BUF_B,   gA_l + ko);
                CP_ASYNC16(so + 2*BUF_B, gB_h + ko);
                CP_ASYNC16(so + 3*BUF_B, gB_l + ko);
            }
            CP_COMMIT();
        }

        const uint32_t stg = smb + (uint32_t)st * STAGE_B;
#pragma unroll
        for (int ks = 0; ks < 2; ks++) {
            const uint32_t kb = (uint32_t)((ks * 16 + lk) * 2);
            uint32_t a_hi[2][4], a_lo[2][4], b_hi[4][2], b_lo[4][2];
#pragma unroll
            for (int mt = 0; mt < 2; mt++) {
                uint32_t ra = stg + (uint32_t)((wr * 32 + mt * 16 + lrow) * TROW) + kb;
                ldsm4(a_hi[mt], ra);
                ldsm4(a_lo[mt], ra + BUF_B);
            }
#pragma unroll
            for (int g = 0; g < 2; g++) {
                uint32_t rb = stg + (uint32_t)((wc * 32 + g * 16 + lrow) * TROW) + kb;
                uint32_t r[4];
                ldsm4(r, rb + 2*BUF_B);
                b_hi[2*g][0] = r[0]; b_hi[2*g][1] = r[2];
                b_hi[2*g+1][0] = r[1]; b_hi[2*g+1][1] = r[3];
                ldsm4(r, rb + 3*BUF_B);
                b_lo[2*g][0] = r[0]; b_lo[2*g][1] = r[2];
                b_lo[2*g+1][0] = r[1]; b_lo[2*g+1][1] = r[3];
            }
#pragma unroll
            for (int mt = 0; mt < 2; mt++)
#pragma unroll
                for (int nt = 0; nt < 4; nt++) {
                    mma16816(c[mt][nt], a_hi[mt], b_hi[nt]);
                    mma16816(c[mt][nt], a_hi[mt], b_lo[nt]);
                    mma16816(c[mt][nt], a_lo[mt], b_hi[nt]);
                }
        }
        st++; if (st >= NSTG) st = 0;
    }
    __syncthreads();
}

// ---------------------------------------------------------------------------
// GEMM1: qkv projection -> bf16 hi/lo Q(scaled)/K/V in [b,h,s,d]
// ---------------------------------------------------------------------------
__global__ __launch_bounds__(512) void gemm_qkv_tc(const float* __restrict__ bqkv)
{
    extern __shared__ char sm[];
    const uint32_t smb = smem_u32(sm);
    const int col0 = blockIdx.x * 128;
    const int row0 = blockIdx.y * 128;
    const int tid = threadIdx.x, wid = tid >> 5, lane = tid & 31;
    const int wr = wid >> 2, wc = wid & 3;

    float c[2][4][4] = {};
    gemm_mainloop(g_xh, g_xl, g_w1h, g_w1l, bqkv, sm, smb, row0, col0, c);

    const float* bias_s = (const float*)(sm + OFF_BIAS);
    const int which = col0 / DD;
    const int h0 = (col0 % DD) / HD;
    const int b_ = row0 >> 12;
    const int s0 = row0 & 4095;
    const float scale = (which == 0) ? 0.125f : 1.0f;

    __nv_bfloat16* dh = (which == 0) ? g_qh : (which == 1) ? g_kh : g_vh;
    __nv_bfloat16* dl = (which == 0) ? g_ql : (which == 1) ? g_kl : g_vl;

#pragma unroll
    for (int mt = 0; mt < 2; mt++)
#pragma unroll
        for (int nt = 0; nt < 4; nt++) {
            int cl = wc * 32 + nt * 8 + (lane & 3) * 2;
            int h  = h0 + (cl >> 6);
            int d  = cl & 63;
            float bx = bias_s[cl], by = bias_s[cl + 1];
            const size_t base = (size_t)(b_ * HH + h) * SS * HD;
#pragma unroll
            for (int hh = 0; hh < 2; hh++) {
                int gs = s0 + wr * 32 + mt * 16 + (lane >> 2) + hh * 8;
                float v0 = (c[mt][nt][2*hh]   + bx) * scale;
                float v1 = (c[mt][nt][2*hh+1] + by) * scale;
                uint32_t hp, lp;
                split2(v0, v1, hp, lp);
                *(uint32_t*)&dh[base + (size_t)gs * HD + d] = hp;
                *(uint32_t*)&dl[base + (size_t)gs * HD + d] = lp;
            }
        }
}

// ---------------------------------------------------------------------------
// GEMM2: out projection
// ---------------------------------------------------------------------------
__global__ __launch_bounds__(512) void gemm_out_tc(const float* __restrict__ bout,
                                                   float* __restrict__ Y)
{
    extern __shared__ char sm[];
    const uint32_t smb = smem_u32(sm);
    const int col0 = blockIdx.x * 128;
    const int row0 = blockIdx.y * 128;
    const int tid = threadIdx.x, wid = tid >> 5, lane = tid & 31;
    const int wr = wid >> 2, wc = wid & 3;

    float c[2][4][4] = {};
    gemm_mainloop(g_oh, g_ol, g_w2h, g_w2l, bout, sm, smb, row0, col0, c);

    const float* bias_s = (const float*)(sm + OFF_BIAS);
#pragma unroll
    for (int mt = 0; mt < 2; mt++)
#pragma unroll
        for (int nt = 0; nt < 4; nt++) {
            int cl = wc * 32 + nt * 8 + (lane & 3) * 2;
            float bx = bias_s[cl], by = bias_s[cl + 1];
#pragma unroll
            for (int hh = 0; hh < 2; hh++) {
                int r = row0 + wr * 32 + mt * 16 + (lane >> 2) + hh * 8;
                float2 v = make_float2(c[mt][nt][2*hh] + bx, c[mt][nt][2*hh+1] + by);
                *(float2*)&Y[(size_t)r * DD + col0 + cl] = v;
            }
        }
}

// ---------------------------------------------------------------------------
// Flash attention on mma.sync (bf16 hi/lo, 3-term) — unchanged (proven).
// ---------------------------------------------------------------------------
#define KST 72
#define QBYTES (128*KST*2)
#define KBYTES (64*KST*2)
#define ATTN_SMEM (4*KBYTES)

__global__ __launch_bounds__(256) void attn_mma_kernel()
{
    extern __shared__ char smc[];
    const uint32_t smb = smem_u32(smc);
    const int qt  = gridDim.x - 1 - blockIdx.x;
    const int bh  = blockIdx.y;
    const int tid = threadIdx.x;
    const int wid = tid >> 5, lane = tid & 31;
    const int lrow = lane & 15, lk = (lane >> 4) * 8;

    const size_t bhoff = (size_t)bh * SS * HD;
    const __nv_bfloat16* Qhg = g_qh + bhoff;
    const __nv_bfloat16* Qlg = g_ql + bhoff;
    const __nv_bfloat16* Khg = g_kh + bhoff;
    const __nv_bfloat16* Klg = g_kl + bhoff;
    const __nv_bfloat16* Vhg = g_vh + bhoff;
    const __nv_bfloat16* Vlg = g_vl + bhoff;

    {
        __nv_bfloat16* qs = (__nv_bfloat16*)smc;
#pragma unroll
        for (int i = 0; i < 4; i++) {
            int f = tid + i * 256;
            int r = f >> 3, c8 = (f & 7) * 8;
            *(uint4*)&qs[r * KST + c8] =
                *(const uint4*)&Qhg[(size_t)(qt * 128 + r) * HD + c8];
            *(uint4*)&qs[128 * KST + r * KST + c8] =
                *(const uint4*)&Qlg[(size_t)(qt * 128 + r) * HD + c8];
        }
    }
    __syncthreads();

    uint32_t qh[4][4], ql[4][4];
#pragma unroll
    for (int t = 0; t < 4; t++) {
        uint32_t a = smb + (uint32_t)((wid * 16 + lrow) * KST + t * 16 + lk) * 2;
        ldsm4(qh[t], a);
        ldsm4(ql[t], a + QBYTES);
    }
    __syncthreads();

    float o[8][4] = {};
    float m0 = -1e30f, m1 = -1e30f, l0 = 0.f, l1 = 0.f;

    const int ktmax = 2 * qt + 1;

    uint4 pk[2][4];
#pragma unroll
    for (int i = 0; i < 2; i++) {
        int f = tid + i * 256;
        int r = f >> 3, c8 = (f & 7) * 8;
        size_t go = (size_t)r * HD + c8;
        pk[i][0] = *(const uint4*)&Khg[go];
        pk[i][1] = *(const uint4*)&Klg[go];
        pk[i][2] = *(const uint4*)&Vhg[go];
        pk[i][3] = *(const uint4*)&Vlg[go];
    }

    for (int kt = 0; kt <= ktmax; kt++) {
        __syncthreads();
        {
            __nv_bfloat16* ks = (__nv_bfloat16*)smc;
#pragma unroll
            for (int i = 0; i < 2; i++) {
                int f = tid + i * 256;
                int r = f >> 3, c8 = (f & 7) * 8;
                int so = r * KST + c8;
                *(uint4*)&ks[so]            = pk[i][0];
                *(uint4*)&ks[64*KST   + so] = pk[i][1];
                *(uint4*)&ks[2*64*KST + so] = pk[i][2];
                *(uint4*)&ks[3*64*KST + so] = pk[i][3];
            }
        }
        __syncthreads();

        if (kt < ktmax) {
#pragma unroll
            for (int i = 0; i < 2; i++) {
                int f = tid + i * 256;
                int r = f >> 3, c8 = (f & 7) * 8;
                size_t go = (size_t)((kt + 1) * 64 + r) * HD + c8;
                pk[i][0] = *(const uint4*)&Khg[go];
                pk[i][1] = *(const uint4*)&Klg[go];
                pk[i][2] = *(const uint4*)&Vhg[go];
                pk[i][3] = *(const uint4*)&Vlg[go];
            }
        }

        float s[8][4] = {};
#pragma unroll
        for (int t = 0; t < 4; t++) {
#pragma unroll
            for (int g = 0; g < 4; g++) {
                uint32_t a = smb + (uint32_t)((g * 16 + lrow) * KST + t * 16 + lk) * 2;
                uint32_t rh[4], rl[4];
                ldsm4(rh, a);
                ldsm4(rl, a + KBYTES);
                uint32_t bh0[2] = {rh[0], rh[2]}, bh1[2] = {rh[1], rh[3]};
                uint32_t bl0[2] = {rl[0], rl[2]}, bl1[2] = {rl[1], rl[3]};
                mma16816(s[2*g],   qh[t], bh0);
                mma16816(s[2*g],   qh[t], bl0);
                mma16816(s[2*g],   ql[t], bh0);
                mma16816(s[2*g+1], qh[t], bh1);
                mma16816(s[2*g+1], qh[t], bl1);
                mma16816(s[2*g+1], ql[t], bh1);
            }
        }

        if (kt * 64 + 63 > qt * 128 + wid * 16) {
            int rbase = qt * 128 + wid * 16 + (lane >> 2);
            int cbase = kt * 64 + (lane & 3) * 2;
#pragma unroll
            for (int n = 0; n < 8; n++) {
                int cc = cbase + n * 8;
                if (cc     > rbase)     s[n][0] = -1e30f;
                if (cc + 1 > rbase)     s[n][1] = -1e30f;
                if (cc     > rbase + 8) s[n][2] = -1e30f;
                if (cc + 1 > rbase + 8) s[n][3] = -1e30f;
            }
        }

        float mx0 = -1e30f, mx1 = -1e30f;
#pragma unroll
        for (int n = 0; n < 8; n++) {
            mx0 = fmaxf(mx0, fmaxf(s[n][0], s[n][1]));
            mx1 = fmaxf(mx1, fmaxf(s[n][2], s[n][3]));
        }
        mx0 = fmaxf(mx0, __shfl_xor_sync(0xffffffffu, mx0, 1));
        mx0 = fmaxf(mx0, __shfl_xor_sync(0xffffffffu, mx0, 2));
        mx1 = fmaxf(mx1, __shfl_xor_sync(0xffffffffu, mx1, 1));
        mx1 = fmaxf(mx1, __shfl_xor_sync(0xffffffffu, mx1, 2));
        float mn0 = fmaxf(m0, mx0), mn1 = fmaxf(m1, mx1);
        float a0 = __expf(m0 - mn0), a1 = __expf(m1 - mn1);
        m0 = mn0; m1 = mn1;
        float lt0 = 0.f, lt1 = 0.f;
#pragma unroll
        for (int n = 0; n < 8; n++) {
            s[n][0] = __expf(s[n][0] - mn0); lt0 += s[n][0];
            s[n][1] = __expf(s[n][1] - mn0); lt0 += s[n][1];
            s[n][2] = __expf(s[n][2] - mn1); lt1 += s[n][2];
            s[n][3] = __expf(s[n][3] - mn1); lt1 += s[n][3];
        }
        lt0 += __shfl_xor_sync(0xffffffffu, lt0, 1);
        lt0 += __shfl_xor_sync(0xffffffffu, lt0, 2);
        lt1 += __shfl_xor_sync(0xffffffffu, lt1, 1);
        lt1 += __shfl_xor_sync(0xffffffffu, lt1, 2);
        l0 = l0 * a0 + lt0;
        l1 = l1 * a1 + lt1;
#pragma unroll
        for (int n = 0; n < 8; n++) {
            o[n][0] *= a0; o[n][1] *= a0; o[n][2] *= a1; o[n][3] *= a1;
        }

#pragma unroll
        for (int t = 0; t < 4; t++) {
            uint32_t ph[4], pl[4];
            split2(s[2*t][0],   s[2*t][1],   ph[0], pl[0]);
            split2(s[2*t][2],   s[2*t][3],   ph[1], pl[1]);
            split2(s[2*t+1][0], s[2*t+1][1], ph[2], pl[2]);
            split2(s[2*t+1][2], s[2*t+1][3], ph[3], pl[3]);
#pragma unroll
            for (int g = 0; g < 4; g++) {
                uint32_t a = smb + (uint32_t)(2*64*KST*2) +
                             (uint32_t)((t * 16 + lrow) * KST + g * 16 + lk) * 2;
                uint32_t rh[4], rl[4];
                ldsm4t(rh, a);
                ldsm4t(rl, a + KBYTES);
                uint32_t bh0[2] = {rh[0], rh[1]}, bh1[2] = {rh[2], rh[3]};
                uint32_t bl0[2] = {rl[0], rl[1]}, bl1[2] = {rl[2], rl[3]};
                mma16816(o[2*g],   ph, bh0);
                mma16816(o[2*g],   ph, bl0);
                mma16816(o[2*g],   pl, bh0);
                mma16816(o[2*g+1], ph, bh1);
                mma16816(o[2*g+1], ph, bl1);
                mma16816(o[2*g+1], pl, bh1);
            }
        }
    }

    float inv0 = 1.f / l0, inv1 = 1.f / l1;
    const int b_ = bh / HH, h_ = bh % HH;
    const size_t r0 = (size_t)(b_ * SS + qt * 128 + wid * 16 + (lane >> 2));
#pragma unroll
    for (int n = 0; n < 8; n++) {
        int d = h_ * 64 + n * 8 + (lane & 3) * 2;
        uint32_t hp, lp;
        split2(o[n][0] * inv0, o[n][1] * inv0, hp, lp);
        *(uint32_t*)&g_oh[r0 * DD + d] = hp;
        *(uint32_t*)&g_ol[r0 * DD + d] = lp;
        split2(o[n][2] * inv1, o[n][3] * inv1, hp, lp);
        *(uint32_t*)&g_oh[(r0 + 8) * DD + d] = hp;
        *(uint32_t*)&g_ol[(r0 + 8) * DD + d] = lp;
    }
}

// ---------------------------------------------------------------------------
extern "C" void kernel_launch(void* const* d_in, const int* in_sizes, int n_in,
                              void* d_out, int out_size)
{
    const float* x    = (const float*)d_in[0];
    const float* Wqkv = (const float*)d_in[1];
    const float* bqkv = (const float*)d_in[2];
    const float* Wout = (const float*)d_in[3];
    const float* bout = (const float*)d_in[4];
    float* out = (float*)d_out;

    cudaFuncSetAttribute(attn_mma_kernel, cudaFuncAttributeMaxDynamicSharedMemorySize, ATTN_SMEM);
    cudaFuncSetAttribute(gemm_qkv_tc, cudaFuncAttributeMaxDynamicSharedMemorySize, GEMM_SMEM);
    cudaFuncSetAttribute(gemm_out_tc, cudaFuncAttributeMaxDynamicSharedMemorySize, GEMM_SMEM);

    __nv_bfloat16 *xh, *xl, *w1h, *w1l, *w2h, *w2l;
    cudaGetSymbolAddress((void**)&xh,  g_xh);  cudaGetSymbolAddress((void**)&xl,  g_xl);
    cudaGetSymbolAddress((void**)&w1h, g_w1h); cudaGetSymbolAddress((void**)&w1l, g_w1l);
    cudaGetSymbolAddress((void**)&w2h, g_w2h); cudaGetSymbolAddress((void**)&w2l, g_w2l);

    split_kernel<<<MM * DD / 1024, 256>>>(x, xh, xl);
    transpose_split_kernel<<<dim3(N3 / 32, DD / 32), dim3(32, 8)>>>(Wqkv, w1h, w1l, DD, N3);
    transpose_split_kernel<<<dim3(DD / 32, DD / 32), dim3(32, 8)>>>(Wout, w2h, w2l, DD, DD);

    gemm_qkv_tc<<<dim3(N3 / 128, MM / 128), 512, GEMM_SMEM>>>(bqkv);
    attn_mma_kernel<<<dim3(SS / 128, BB * HH), 256, ATTN_SMEM>>>();
    gemm_out_tc<<<dim3(DD / 128, MM / 128), 512, GEMM_SMEM>>>(bout, out);
}